// round 2
// baseline (speedup 1.0000x reference)
#include <cuda_runtime.h>
#include <math.h>

#define BB 2
#define SEQ 4096
#define DM 256
#define NH 8
#define HD 32
#define DFF 1024
#define MROWS (BB*SEQ)   // 8192

// ---- scratch (device globals; no allocation allowed) ----
__device__ float g_xn1 [MROWS*DM];
__device__ float g_q   [MROWS*DM];
__device__ float g_k   [MROWS*DM];
__device__ float g_v   [MROWS*DM];
__device__ float g_attn[MROWS*DM];
__device__ float g_xskip[MROWS*DM];
__device__ float g_xn2 [MROWS*DM];
__device__ float g_h1  [MROWS*DFF];

// ---------------- LayerNorm: (x-mean)/(std+1e-6), one block per row ----------------
__global__ __launch_bounds__(256)
void ln_kernel(const float* __restrict__ x, float* __restrict__ y) {
    int row = blockIdx.x;
    int tid = threadIdx.x;
    float v = x[row*DM + tid];
    float s = v, s2 = v*v;
    #pragma unroll
    for (int o = 16; o; o >>= 1) {
        s  += __shfl_xor_sync(0xffffffffu, s,  o);
        s2 += __shfl_xor_sync(0xffffffffu, s2, o);
    }
    __shared__ float ss[8], ss2[8];
    int w = tid >> 5, l = tid & 31;
    if (l == 0) { ss[w] = s; ss2[w] = s2; }
    __syncthreads();
    float tot = 0.f, tot2 = 0.f;
    #pragma unroll
    for (int i = 0; i < 8; i++) { tot += ss[i]; tot2 += ss2[i]; }
    float m   = tot * (1.0f/DM);
    float var = tot2 * (1.0f/DM) - m*m;
    float inv = 1.0f / (sqrtf(fmaxf(var, 0.f)) + 1e-6f);
    y[row*DM + tid] = (v - m) * inv;
}

// ---------------- Tiled GEMM: out[M,N] = A[M,K] @ W[K,N] + bias (+ epilogues) ----------------
// EP 0: +bias   EP 1: +bias+res   EP 2: gelu(+bias)   EP 3: +bias+res
template<int EP>
__global__ __launch_bounds__(256)
void gemm_kernel(const float* __restrict__ A, const float* __restrict__ Wm,
                 const float* __restrict__ bias, const float* __restrict__ res,
                 float* __restrict__ out, int M, int N, int K) {
    __shared__ float As[16][128];
    __shared__ float Bs[16][64];
    int t  = threadIdx.x;
    int tx = t & 15, ty = t >> 4;        // 16 x 16 threads, each 8x4 outputs
    int m0 = blockIdx.y * 128;
    int n0 = blockIdx.x * 64;
    float acc[8][4] = {};
    for (int k0 = 0; k0 < K; k0 += 16) {
        #pragma unroll
        for (int i = 0; i < 2; i++) {
            int idx  = t*2 + i;          // 0..511
            int arow = idx >> 2, c4 = idx & 3;
            float4 av = *(const float4*)&A[(size_t)(m0+arow)*K + k0 + c4*4];
            As[c4*4+0][arow] = av.x; As[c4*4+1][arow] = av.y;
            As[c4*4+2][arow] = av.z; As[c4*4+3][arow] = av.w;
        }
        {
            int kr = t >> 4, c4 = t & 15;
            *(float4*)&Bs[kr][c4*4] = *(const float4*)&Wm[(size_t)(k0+kr)*N + n0 + c4*4];
        }
        __syncthreads();
        #pragma unroll
        for (int kk = 0; kk < 16; kk++) {
            float a[8], b[4];
            *(float4*)&a[0] = *(const float4*)&As[kk][ty*8];
            *(float4*)&a[4] = *(const float4*)&As[kk][ty*8+4];
            *(float4*)&b[0] = *(const float4*)&Bs[kk][tx*4];
            #pragma unroll
            for (int i = 0; i < 8; i++)
                #pragma unroll
                for (int j = 0; j < 4; j++)
                    acc[i][j] += a[i]*b[j];
        }
        __syncthreads();
    }
    #pragma unroll
    for (int i = 0; i < 8; i++) {
        int row = m0 + ty*8 + i;
        #pragma unroll
        for (int j = 0; j < 4; j++) {
            int col = n0 + tx*4 + j;
            float val = acc[i][j] + bias[col];
            if (EP == 1 || EP == 3) val += res[(size_t)row*N + col];
            if (EP == 2) {
                float u = val;
                float inner = 0.7978845608028654f * (u + 0.044715f*u*u*u);
                val = 0.5f * u * (1.0f + tanhf(inner));
            }
            out[(size_t)row*N + col] = val;
        }
    }
}

// ---------------- Flash attention: one thread per query row, 32-key tiles ----------------
__global__ __launch_bounds__(128)
void attn_kernel() {
    int bh = blockIdx.x;                 // 0..15
    int b  = bh >> 3, h = bh & 7;
    int row = blockIdx.y * 128 + threadIdx.x;

    const float* qp = &g_q[(size_t)(b*SEQ + row)*DM + h*HD];
    float q[HD];
    #pragma unroll
    for (int c4 = 0; c4 < 8; c4++) {
        float4 qv = *(const float4*)&qp[c4*4];
        q[c4*4+0]=qv.x; q[c4*4+1]=qv.y; q[c4*4+2]=qv.z; q[c4*4+3]=qv.w;
    }
    float O[HD] = {};
    float mx = -1e30f, l = 0.f;
    __shared__ float Ks[32][HD];
    __shared__ float Vs[32][HD];
    const float scale = 0.17677669529663687f;  // 1/sqrt(32)
    const float* kbase = &g_k[(size_t)b*SEQ*DM + h*HD];
    const float* vbase = &g_v[(size_t)b*SEQ*DM + h*HD];

    for (int t0 = 0; t0 < SEQ; t0 += 32) {
        #pragma unroll
        for (int i = 0; i < 2; i++) {
            int idx = threadIdx.x*2 + i;     // 0..255
            int key = idx >> 3, c4 = idx & 7;
            *(float4*)&Ks[key][c4*4] = *(const float4*)&kbase[(size_t)(t0+key)*DM + c4*4];
            *(float4*)&Vs[key][c4*4] = *(const float4*)&vbase[(size_t)(t0+key)*DM + c4*4];
        }
        __syncthreads();

        float s[32];
        float tmax = -1e30f;
        #pragma unroll
        for (int j = 0; j < 32; j++) {
            float acc = 0.f;
            #pragma unroll
            for (int c4 = 0; c4 < 8; c4++) {
                float4 kv = *(const float4*)&Ks[j][c4*4];
                acc += q[c4*4+0]*kv.x + q[c4*4+1]*kv.y
                     + q[c4*4+2]*kv.z + q[c4*4+3]*kv.w;
            }
            s[j] = acc * scale;
            tmax = fmaxf(tmax, s[j]);
        }
        float mnew = fmaxf(mx, tmax);
        float corr = __expf(mx - mnew);
        l *= corr;
        #pragma unroll
        for (int c = 0; c < HD; c++) O[c] *= corr;
        #pragma unroll
        for (int j = 0; j < 32; j++) {
            float p = __expf(s[j] - mnew);
            l += p;
            #pragma unroll
            for (int c4 = 0; c4 < 8; c4++) {
                float4 vv = *(const float4*)&Vs[j][c4*4];
                O[c4*4+0] += p*vv.x; O[c4*4+1] += p*vv.y;
                O[c4*4+2] += p*vv.z; O[c4*4+3] += p*vv.w;
            }
        }
        mx = mnew;
        __syncthreads();
    }
    float inv = 1.f / l;
    float* op = &g_attn[(size_t)(b*SEQ + row)*DM + h*HD];
    #pragma unroll
    for (int c = 0; c < HD; c++) op[c] = O[c]*inv;
}

extern "C" void kernel_launch(void* const* d_in, const int* in_sizes, int n_in,
                              void* d_out, int out_size) {
    const float* x  = (const float*)d_in[0];
    const float* Wq = (const float*)d_in[1];
    const float* bq = (const float*)d_in[2];
    const float* Wk = (const float*)d_in[3];
    const float* bk = (const float*)d_in[4];
    const float* Wv = (const float*)d_in[5];
    const float* bv = (const float*)d_in[6];
    const float* Wo = (const float*)d_in[7];
    const float* bo = (const float*)d_in[8];
    const float* W1 = (const float*)d_in[9];
    const float* b1 = (const float*)d_in[10];
    const float* W2 = (const float*)d_in[11];
    const float* b2 = (const float*)d_in[12];
    float* out = (float*)d_out;

    float *xn1, *q, *k, *v, *attn, *xskip, *xn2, *h1;
    cudaGetSymbolAddress((void**)&xn1,  g_xn1);
    cudaGetSymbolAddress((void**)&q,    g_q);
    cudaGetSymbolAddress((void**)&k,    g_k);
    cudaGetSymbolAddress((void**)&v,    g_v);
    cudaGetSymbolAddress((void**)&attn, g_attn);
    cudaGetSymbolAddress((void**)&xskip,g_xskip);
    cudaGetSymbolAddress((void**)&xn2,  g_xn2);
    cudaGetSymbolAddress((void**)&h1,   g_h1);

    dim3 gD (DM/64,  MROWS/128);   // N=256 outputs
    dim3 gF (DFF/64, MROWS/128);   // N=1024 outputs

    ln_kernel<<<MROWS, 256>>>(x, xn1);
    gemm_kernel<0><<<gD, 256>>>(xn1, Wq, bq, nullptr, q, MROWS, DM, DM);
    gemm_kernel<0><<<gD, 256>>>(xn1, Wk, bk, nullptr, k, MROWS, DM, DM);
    gemm_kernel<0><<<gD, 256>>>(xn1, Wv, bv, nullptr, v, MROWS, DM, DM);
    attn_kernel<<<dim3(BB*NH, SEQ/128), 128>>>();
    gemm_kernel<1><<<gD, 256>>>(attn, Wo, bo, x, xskip, MROWS, DM, DM);
    ln_kernel<<<MROWS, 256>>>(xskip, xn2);
    gemm_kernel<2><<<gF, 256>>>(xn2, W1, b1, nullptr, h1, MROWS, DFF, DM);
    gemm_kernel<3><<<gD, 256>>>(h1, W2, b2, xskip, out, MROWS, DM, DFF);
}

// round 3
// speedup vs baseline: 1.8450x; 1.8450x over previous
#include <cuda_runtime.h>
#include <math.h>
#include <stdint.h>

#define BB 2
#define SEQ 4096
#define DM 256
#define NH 8
#define HD 32
#define DFF 1024
#define MROWS (BB*SEQ)   // 8192
#define SPLIT 2
#define KHALF (SEQ/SPLIT)

typedef unsigned long long u64;

// ---- scratch (device globals; no allocation allowed) ----
__device__ float g_xn1 [MROWS*DM];
__device__ float g_q   [MROWS*DM];
__device__ float g_k   [MROWS*DM];
__device__ float g_v   [MROWS*DM];
__device__ float g_attn[MROWS*DM];
__device__ float g_xskip[MROWS*DM];
__device__ float g_xn2 [MROWS*DM];
__device__ float g_h1  [MROWS*DFF];
__device__ float g_opart[SPLIT][MROWS*DM];
__device__ float g_m  [SPLIT][MROWS*NH];
__device__ float g_l  [SPLIT][MROWS*NH];

// ---------------- packed f32x2 helpers (sm_100+) ----------------
__device__ __forceinline__ u64 pk2(float x, float y){ u64 r; asm("mov.b64 %0,{%1,%2};":"=l"(r):"f"(x),"f"(y)); return r; }
__device__ __forceinline__ void upk2(u64 v, float&x, float&y){ asm("mov.b64 {%0,%1},%2;":"=f"(x),"=f"(y):"l"(v)); }
__device__ __forceinline__ u64 fma2(u64 a,u64 b,u64 c){ u64 d; asm("fma.rn.f32x2 %0,%1,%2,%3;":"=l"(d):"l"(a),"l"(b),"l"(c)); return d; }
__device__ __forceinline__ u64 mul2(u64 a,u64 b){ u64 d; asm("mul.rn.f32x2 %0,%1,%2;":"=l"(d):"l"(a),"l"(b)); return d; }
__device__ __forceinline__ uint32_t tf32(float x){ uint32_t r; asm("cvt.rna.tf32.f32 %0,%1;":"=r"(r):"f"(x)); return r; }

// ---------------- LayerNorm ----------------
__global__ __launch_bounds__(256)
void ln_kernel(const float* __restrict__ x, float* __restrict__ y) {
    int row = blockIdx.x;
    int tid = threadIdx.x;
    float v = x[row*DM + tid];
    float s = v, s2 = v*v;
    #pragma unroll
    for (int o = 16; o; o >>= 1) {
        s  += __shfl_xor_sync(0xffffffffu, s,  o);
        s2 += __shfl_xor_sync(0xffffffffu, s2, o);
    }
    __shared__ float ss[8], ss2[8];
    int w = tid >> 5, l = tid & 31;
    if (l == 0) { ss[w] = s; ss2[w] = s2; }
    __syncthreads();
    float tot = 0.f, tot2 = 0.f;
    #pragma unroll
    for (int i = 0; i < 8; i++) { tot += ss[i]; tot2 += ss2[i]; }
    float m   = tot * (1.0f/DM);
    float var = tot2 * (1.0f/DM) - m*m;
    float inv = 1.0f / (sqrtf(fmaxf(var, 0.f)) + 1e-6f);
    y[row*DM + tid] = (v - m) * inv;
}

// ---------------- tf32 tensor-core GEMM ----------------
// out[M,N] = A[M,K] @ W[K,N] + bias; EP1/3 add res, EP2 gelu.
// Block: 256 thr, 8 warps (2m x 4n). Block tile 64x256, warp tile 32x64, BK=16.
template<int EP>
__global__ __launch_bounds__(256)
void mma_gemm(const float* __restrict__ A, const float* __restrict__ Wm,
              const float* __restrict__ bias, const float* __restrict__ res,
              float* __restrict__ out, int M, int N, int K) {
    __shared__ uint32_t As[64][20];    // row-major, pad 20 -> frag reads conflict-free
    __shared__ uint32_t Bs[16][264];   // row-major, pad 264 -> frag reads conflict-free
    int tid = threadIdx.x, lane = tid & 31, warp = tid >> 5;
    int wm = warp & 1, wn = warp >> 1;           // 2 x 4 warps
    int m0 = blockIdx.y * 64, n0 = blockIdx.x * 256;
    int g = lane >> 2, tg = lane & 3;
    float c[2][8][4];
    #pragma unroll
    for (int i=0;i<2;i++) 
        #pragma unroll
        for(int j=0;j<8;j++) 
            #pragma unroll
            for(int q=0;q<4;q++) c[i][j][q]=0.f;

    for (int k0 = 0; k0 < K; k0 += 16) {
        {   // A tile 64x16
            int r = tid >> 2, c4 = (tid & 3) * 4;
            float4 v = *(const float4*)&A[(size_t)(m0+r)*K + k0 + c4];
            uint4 u; u.x=tf32(v.x); u.y=tf32(v.y); u.z=tf32(v.z); u.w=tf32(v.w);
            *(uint4*)&As[r][c4] = u;
        }
        #pragma unroll
        for (int i = 0; i < 4; i++) {   // B tile 16x256
            int idx = tid + i*256;
            int r = idx >> 6, cc = (idx & 63) * 4;
            float4 v = *(const float4*)&Wm[(size_t)(k0+r)*N + n0 + cc];
            uint4 u; u.x=tf32(v.x); u.y=tf32(v.y); u.z=tf32(v.z); u.w=tf32(v.w);
            *(uint4*)&Bs[r][cc] = u;
        }
        __syncthreads();
        #pragma unroll
        for (int ks = 0; ks < 2; ks++) {
            int kb = ks * 8;
            uint32_t a[2][4];
            #pragma unroll
            for (int mt = 0; mt < 2; mt++) {
                int r = wm*32 + mt*16;
                a[mt][0] = As[r+g  ][kb+tg  ];
                a[mt][1] = As[r+g+8][kb+tg  ];
                a[mt][2] = As[r+g  ][kb+tg+4];
                a[mt][3] = As[r+g+8][kb+tg+4];
            }
            uint32_t b[8][2];
            #pragma unroll
            for (int nt = 0; nt < 8; nt++) {
                int col = wn*64 + nt*8 + g;
                b[nt][0] = Bs[kb+tg  ][col];
                b[nt][1] = Bs[kb+tg+4][col];
            }
            #pragma unroll
            for (int mt = 0; mt < 2; mt++)
                #pragma unroll
                for (int nt = 0; nt < 8; nt++)
                    asm volatile(
                        "mma.sync.aligned.m16n8k8.row.col.f32.tf32.tf32.f32 "
                        "{%0,%1,%2,%3}, {%4,%5,%6,%7}, {%8,%9}, {%0,%1,%2,%3};"
                        : "+f"(c[mt][nt][0]), "+f"(c[mt][nt][1]),
                          "+f"(c[mt][nt][2]), "+f"(c[mt][nt][3])
                        : "r"(a[mt][0]), "r"(a[mt][1]), "r"(a[mt][2]), "r"(a[mt][3]),
                          "r"(b[nt][0]), "r"(b[nt][1]));
        }
        __syncthreads();
    }
    // epilogue
    #pragma unroll
    for (int mt = 0; mt < 2; mt++) {
        #pragma unroll
        for (int nt = 0; nt < 8; nt++) {
            int col = n0 + wn*64 + nt*8 + 2*tg;
            float2 bv = *(const float2*)&bias[col];
            #pragma unroll
            for (int half = 0; half < 2; half++) {
                int row = m0 + wm*32 + mt*16 + g + half*8;
                float v0 = c[mt][nt][half*2+0] + bv.x;
                float v1 = c[mt][nt][half*2+1] + bv.y;
                if (EP == 1 || EP == 3) {
                    float2 rv = *(const float2*)&res[(size_t)row*N + col];
                    v0 += rv.x; v1 += rv.y;
                }
                if (EP == 2) {
                    float i0 = 0.7978845608028654f * (v0 + 0.044715f*v0*v0*v0);
                    float i1 = 0.7978845608028654f * (v1 + 0.044715f*v1*v1*v1);
                    v0 = 0.5f * v0 * (1.0f + tanhf(i0));
                    v1 = 0.5f * v1 * (1.0f + tanhf(i1));
                }
                float2 o; o.x = v0; o.y = v1;
                *(float2*)&out[(size_t)row*N + col] = o;
            }
        }
    }
}

// ---------------- Flash attention, split-K=2, 2 rows/thread, f32x2 math ----------------
__global__ __launch_bounds__(128)
void attn_kernel() {
    int bh = blockIdx.x;                 // 0..15
    int b  = bh >> 3, h = bh & 7;
    int sp = blockIdx.z;
    int r0 = (blockIdx.y * 128 + threadIdx.x) * 2;   // two rows per thread

    const float* qbase = &g_q[(size_t)(b*SEQ)*DM + h*HD];
    const float* kbase = &g_k[(size_t)b*SEQ*DM + h*HD];
    const float* vbase = &g_v[(size_t)b*SEQ*DM + h*HD];

    u64 q[2][16], O[2][16];
    #pragma unroll
    for (int r = 0; r < 2; r++)
        #pragma unroll
        for (int c = 0; c < 8; c++) {
            ulonglong2 qv = *(const ulonglong2*)&qbase[(size_t)(r0+r)*DM + c*4];
            q[r][2*c] = qv.x; q[r][2*c+1] = qv.y;
            O[r][2*c] = 0ull; O[r][2*c+1] = 0ull;
        }
    float mx[2] = {-1e30f, -1e30f}, l[2] = {0.f, 0.f};

    __shared__ float Ks[16][HD];
    __shared__ float Vs[16][HD];
    const float scale = 0.17677669529663687f;  // 1/sqrt(32)

    int kstart = sp * KHALF;
    for (int t0 = kstart; t0 < kstart + KHALF; t0 += 16) {
        {   // 128 threads load 16x32 K + 16x32 V (one float4 each)
            int key = threadIdx.x >> 3, c4 = (threadIdx.x & 7) * 4;
            *(float4*)&Ks[key][c4] = *(const float4*)&kbase[(size_t)(t0+key)*DM + c4];
            *(float4*)&Vs[key][c4] = *(const float4*)&vbase[(size_t)(t0+key)*DM + c4];
        }
        __syncthreads();

        float s[2][16];
        float tmax[2] = {-1e30f, -1e30f};
        #pragma unroll
        for (int j = 0; j < 16; j++) {
            u64 a0 = 0ull, a1 = 0ull;
            #pragma unroll
            for (int c = 0; c < 8; c++) {
                ulonglong2 kv = *(const ulonglong2*)&Ks[j][c*4];
                a0 = fma2(q[0][2*c], kv.x, a0);
                a0 = fma2(q[0][2*c+1], kv.y, a0);
                a1 = fma2(q[1][2*c], kv.x, a1);
                a1 = fma2(q[1][2*c+1], kv.y, a1);
            }
            float x0,y0,x1,y1;
            upk2(a0,x0,y0); upk2(a1,x1,y1);
            s[0][j] = (x0+y0)*scale; s[1][j] = (x1+y1)*scale;
            tmax[0] = fmaxf(tmax[0], s[0][j]);
            tmax[1] = fmaxf(tmax[1], s[1][j]);
        }
        #pragma unroll
        for (int r = 0; r < 2; r++) {
            float mnew = fmaxf(mx[r], tmax[r]);
            float corr = __expf(mx[r] - mnew);
            l[r] *= corr;
            u64 c2 = pk2(corr, corr);
            #pragma unroll
            for (int i = 0; i < 16; i++) O[r][i] = mul2(O[r][i], c2);
            mx[r] = mnew;
        }
        #pragma unroll
        for (int j = 0; j < 16; j++) {
            float p0 = __expf(s[0][j] - mx[0]);
            float p1 = __expf(s[1][j] - mx[1]);
            l[0] += p0; l[1] += p1;
            u64 pp0 = pk2(p0, p0), pp1 = pk2(p1, p1);
            #pragma unroll
            for (int c = 0; c < 8; c++) {
                ulonglong2 vv = *(const ulonglong2*)&Vs[j][c*4];
                O[0][2*c]   = fma2(pp0, vv.x, O[0][2*c]);
                O[0][2*c+1] = fma2(pp0, vv.y, O[0][2*c+1]);
                O[1][2*c]   = fma2(pp1, vv.x, O[1][2*c]);
                O[1][2*c+1] = fma2(pp1, vv.y, O[1][2*c+1]);
            }
        }
        __syncthreads();
    }
    #pragma unroll
    for (int r = 0; r < 2; r++) {
        int rowg = b*SEQ + r0 + r;
        float inv = 1.f / l[r];
        float* op = &g_opart[sp][(size_t)rowg*DM + h*HD];
        #pragma unroll
        for (int c = 0; c < 8; c++) {
            float x0,y0,x1,y1;
            upk2(O[r][2*c], x0, y0); upk2(O[r][2*c+1], x1, y1);
            float4 ov; ov.x=x0*inv; ov.y=y0*inv; ov.z=x1*inv; ov.w=y1*inv;
            *(float4*)&op[c*4] = ov;
        }
        g_m[sp][rowg*NH + h] = mx[r];
        g_l[sp][rowg*NH + h] = l[r];
    }
}

// ---------------- merge the two K-splits ----------------
__global__ __launch_bounds__(256)
void merge_kernel() {
    int row = blockIdx.x;            // 0..8191
    int col = threadIdx.x;           // 0..255
    int h = col >> 5;
    float m0 = g_m[0][row*NH+h], m1 = g_m[1][row*NH+h];
    float l0 = g_l[0][row*NH+h], l1 = g_l[1][row*NH+h];
    float M = fmaxf(m0, m1);
    float w0 = l0 * __expf(m0 - M);
    float w1 = l1 * __expf(m1 - M);
    float o0 = g_opart[0][(size_t)row*DM + col];
    float o1 = g_opart[1][(size_t)row*DM + col];
    g_attn[(size_t)row*DM + col] = (w0*o0 + w1*o1) / (w0 + w1);
}

extern "C" void kernel_launch(void* const* d_in, const int* in_sizes, int n_in,
                              void* d_out, int out_size) {
    const float* x  = (const float*)d_in[0];
    const float* Wq = (const float*)d_in[1];
    const float* bq = (const float*)d_in[2];
    const float* Wk = (const float*)d_in[3];
    const float* bk = (const float*)d_in[4];
    const float* Wv = (const float*)d_in[5];
    const float* bv = (const float*)d_in[6];
    const float* Wo = (const float*)d_in[7];
    const float* bo = (const float*)d_in[8];
    const float* W1 = (const float*)d_in[9];
    const float* b1 = (const float*)d_in[10];
    const float* W2 = (const float*)d_in[11];
    const float* b2 = (const float*)d_in[12];
    float* out = (float*)d_out;

    float *xn1, *q, *k, *v, *attn, *xskip, *xn2, *h1;
    cudaGetSymbolAddress((void**)&xn1,  g_xn1);
    cudaGetSymbolAddress((void**)&q,    g_q);
    cudaGetSymbolAddress((void**)&k,    g_k);
    cudaGetSymbolAddress((void**)&v,    g_v);
    cudaGetSymbolAddress((void**)&attn, g_attn);
    cudaGetSymbolAddress((void**)&xskip,g_xskip);
    cudaGetSymbolAddress((void**)&xn2,  g_xn2);
    cudaGetSymbolAddress((void**)&h1,   g_h1);

    dim3 gD (DM/256,  MROWS/64);    // (1,128)
    dim3 gF (DFF/256, MROWS/64);    // (4,128)

    ln_kernel<<<MROWS, 256>>>(x, xn1);
    mma_gemm<0><<<gD, 256>>>(xn1, Wq, bq, nullptr, q, MROWS, DM, DM);
    mma_gemm<0><<<gD, 256>>>(xn1, Wk, bk, nullptr, k, MROWS, DM, DM);
    mma_gemm<0><<<gD, 256>>>(xn1, Wv, bv, nullptr, v, MROWS, DM, DM);
    attn_kernel<<<dim3(BB*NH, SEQ/256, SPLIT), 128>>>();
    merge_kernel<<<MROWS, 256>>>();
    mma_gemm<1><<<gD, 256>>>(attn, Wo, bo, x, xskip, MROWS, DM, DM);
    ln_kernel<<<MROWS, 256>>>(xskip, xn2);
    mma_gemm<2><<<gF, 256>>>(xn2, W1, b1, nullptr, h1, MROWS, DFF, DM);
    mma_gemm<3><<<gD, 256>>>(h1, W2, b2, xskip, out, MROWS, DM, DFF);
}

// round 5
// speedup vs baseline: 3.5753x; 1.9379x over previous
#include <cuda_runtime.h>
#include <math.h>
#include <stdint.h>

#define BB 2
#define SEQ 4096
#define DM 256
#define NH 8
#define HD 32
#define DFF 1024
#define MROWS (BB*SEQ)   // 8192

// ---- scratch (device globals; no allocation allowed) ----
__device__ float g_xn1 [MROWS*DM];
__device__ float g_q   [MROWS*DM];
__device__ float g_k   [MROWS*DM];
__device__ float g_v   [MROWS*DM];
__device__ float g_attn[MROWS*DM];
__device__ float g_xskip[MROWS*DM];
__device__ float g_xn2 [MROWS*DM];
__device__ float g_h1  [MROWS*DFF];

__device__ __forceinline__ uint32_t tf32(float x){ uint32_t r; asm("cvt.rna.tf32.f32 %0,%1;":"=r"(r):"f"(x)); return r; }

__device__ __forceinline__ void mma8(float c[4], const uint32_t a[4], const uint32_t b[2]) {
    asm volatile(
        "mma.sync.aligned.m16n8k8.row.col.f32.tf32.tf32.f32 "
        "{%0,%1,%2,%3}, {%4,%5,%6,%7}, {%8,%9}, {%0,%1,%2,%3};"
        : "+f"(c[0]), "+f"(c[1]), "+f"(c[2]), "+f"(c[3])
        : "r"(a[0]), "r"(a[1]), "r"(a[2]), "r"(a[3]), "r"(b[0]), "r"(b[1]));
}

// ---------------- LayerNorm ----------------
__global__ __launch_bounds__(256)
void ln_kernel(const float* __restrict__ x, float* __restrict__ y) {
    int row = blockIdx.x;
    int tid = threadIdx.x;
    float v = x[row*DM + tid];
    float s = v, s2 = v*v;
    #pragma unroll
    for (int o = 16; o; o >>= 1) {
        s  += __shfl_xor_sync(0xffffffffu, s,  o);
        s2 += __shfl_xor_sync(0xffffffffu, s2, o);
    }
    __shared__ float ss[8], ss2[8];
    int w = tid >> 5, l = tid & 31;
    if (l == 0) { ss[w] = s; ss2[w] = s2; }
    __syncthreads();
    float tot = 0.f, tot2 = 0.f;
    #pragma unroll
    for (int i = 0; i < 8; i++) { tot += ss[i]; tot2 += ss2[i]; }
    float m   = tot * (1.0f/DM);
    float var = tot2 * (1.0f/DM) - m*m;
    float inv = 1.0f / (sqrtf(fmaxf(var, 0.f)) + 1e-6f);
    y[row*DM + tid] = (v - m) * inv;
}

// ---------------- tf32 tensor-core GEMM ----------------
template<int EP>
__global__ __launch_bounds__(256)
void mma_gemm(const float* __restrict__ A, const float* __restrict__ Wm,
              const float* __restrict__ bias, const float* __restrict__ res,
              float* __restrict__ out, int M, int N, int K) {
    __shared__ uint32_t As[64][20];
    __shared__ uint32_t Bs[16][264];
    int tid = threadIdx.x, lane = tid & 31, warp = tid >> 5;
    int wm = warp & 1, wn = warp >> 1;
    int m0 = blockIdx.y * 64, n0 = blockIdx.x * 256;
    int g = lane >> 2, tg = lane & 3;
    float c[2][8][4];
    #pragma unroll
    for (int i=0;i<2;i++)
        #pragma unroll
        for(int j=0;j<8;j++)
            #pragma unroll
            for(int q=0;q<4;q++) c[i][j][q]=0.f;

    for (int k0 = 0; k0 < K; k0 += 16) {
        {
            int r = tid >> 2, c4 = (tid & 3) * 4;
            float4 v = *(const float4*)&A[(size_t)(m0+r)*K + k0 + c4];
            uint4 u; u.x=tf32(v.x); u.y=tf32(v.y); u.z=tf32(v.z); u.w=tf32(v.w);
            *(uint4*)&As[r][c4] = u;
        }
        #pragma unroll
        for (int i = 0; i < 4; i++) {
            int idx = tid + i*256;
            int r = idx >> 6, cc = (idx & 63) * 4;
            float4 v = *(const float4*)&Wm[(size_t)(k0+r)*N + n0 + cc];
            uint4 u; u.x=tf32(v.x); u.y=tf32(v.y); u.z=tf32(v.z); u.w=tf32(v.w);
            *(uint4*)&Bs[r][cc] = u;
        }
        __syncthreads();
        #pragma unroll
        for (int ks = 0; ks < 2; ks++) {
            int kb = ks * 8;
            uint32_t a[2][4];
            #pragma unroll
            for (int mt = 0; mt < 2; mt++) {
                int r = wm*32 + mt*16;
                a[mt][0] = As[r+g  ][kb+tg  ];
                a[mt][1] = As[r+g+8][kb+tg  ];
                a[mt][2] = As[r+g  ][kb+tg+4];
                a[mt][3] = As[r+g+8][kb+tg+4];
            }
            uint32_t b[8][2];
            #pragma unroll
            for (int nt = 0; nt < 8; nt++) {
                int col = wn*64 + nt*8 + g;
                b[nt][0] = Bs[kb+tg  ][col];
                b[nt][1] = Bs[kb+tg+4][col];
            }
            #pragma unroll
            for (int mt = 0; mt < 2; mt++)
                #pragma unroll
                for (int nt = 0; nt < 8; nt++)
                    mma8(c[mt][nt], a[mt], b[nt]);
        }
        __syncthreads();
    }
    #pragma unroll
    for (int mt = 0; mt < 2; mt++) {
        #pragma unroll
        for (int nt = 0; nt < 8; nt++) {
            int col = n0 + wn*64 + nt*8 + 2*tg;
            float2 bv = *(const float2*)&bias[col];
            #pragma unroll
            for (int half = 0; half < 2; half++) {
                int row = m0 + wm*32 + mt*16 + g + half*8;
                float v0 = c[mt][nt][half*2+0] + bv.x;
                float v1 = c[mt][nt][half*2+1] + bv.y;
                if (EP == 1 || EP == 3) {
                    float2 rv = *(const float2*)&res[(size_t)row*N + col];
                    v0 += rv.x; v1 += rv.y;
                }
                if (EP == 2) {
                    float i0 = 0.7978845608028654f * (v0 + 0.044715f*v0*v0*v0);
                    float i1 = 0.7978845608028654f * (v1 + 0.044715f*v1*v1*v1);
                    v0 = 0.5f * v0 * (1.0f + tanhf(i0));
                    v1 = 0.5f * v1 * (1.0f + tanhf(i1));
                }
                float2 o; o.x = v0; o.y = v1;
                *(float2*)&out[(size_t)row*N + col] = o;
            }
        }
    }
}

// ---------------- Tensor-core flash attention ----------------
#define KST 36   // Ks row stride
#define VST 40   // Vs row stride
#define NT_KEYS (SEQ/64)

__global__ __launch_bounds__(128)
void attn_mma() {
    __shared__ __align__(16) uint32_t sraw[2*64*KST + 2*64*VST];  // 38912 B
    float*    Qs = (float*)sraw;                 // [128][33] phase 1 only
    uint32_t* Kb = sraw;                         // [2][64][KST]
    uint32_t* Vb = sraw + 2*64*KST;              // [2][64][VST]

    int qt = blockIdx.x;          // 0..31
    int bh = blockIdx.y;          // 0..15
    int b = bh >> 3, h = bh & 7;
    int tid = threadIdx.x, lane = tid & 31, w = tid >> 5;
    int g = lane >> 2, tg = lane & 3;

    const float scale = 0.17677669529663687f;    // 1/sqrt(32)
    const float* qg = &g_q[((size_t)(b*SEQ + qt*128))*DM + h*HD];
    const float* kg = &g_k[(size_t)b*SEQ*DM + h*HD];
    const float* vg = &g_v[(size_t)b*SEQ*DM + h*HD];

    // ---- load Q tile (scaled), build persistent A fragments ----
    #pragma unroll
    for (int i = 0; i < 8; i++) {
        int e = tid + i*128;
        int r = e >> 3, c4 = (e & 7)*4;
        float4 v = *(const float4*)&qg[(size_t)r*DM + c4];
        Qs[r*33+c4+0]=v.x*scale; Qs[r*33+c4+1]=v.y*scale;
        Qs[r*33+c4+2]=v.z*scale; Qs[r*33+c4+3]=v.w*scale;
    }
    __syncthreads();
    uint32_t aQ[2][4][4];
    #pragma unroll
    for (int mt = 0; mt < 2; mt++)
        #pragma unroll
        for (int kc = 0; kc < 4; kc++) {
            int r = w*32 + mt*16;
            aQ[mt][kc][0] = tf32(Qs[(r+g  )*33 + kc*8+tg  ]);
            aQ[mt][kc][1] = tf32(Qs[(r+g+8)*33 + kc*8+tg  ]);
            aQ[mt][kc][2] = tf32(Qs[(r+g  )*33 + kc*8+tg+4]);
            aQ[mt][kc][3] = tf32(Qs[(r+g+8)*33 + kc*8+tg+4]);
        }
    __syncthreads();   // Qs region about to be reused as K/V buffers

    float O[2][4][4];
    #pragma unroll
    for (int mt=0;mt<2;mt++)
        #pragma unroll
        for (int nt=0;nt<4;nt++)
            #pragma unroll
            for (int q=0;q<4;q++) O[mt][nt][q]=0.f;
    float m[2][2] = {{-1e30f,-1e30f},{-1e30f,-1e30f}};
    float lsum[2][2] = {{0.f,0.f},{0.f,0.f}};

    // loader: 64x32 tile = 512 float4; 128 threads x 4 float4 each (rows pr+j*16)
    int pr = tid >> 3, pc = (tid & 7)*4;
    float4 fk[4], fv[4];
    #pragma unroll
    for (int j = 0; j < 4; j++) {
        fk[j] = *(const float4*)&kg[(size_t)(pr + j*16)*DM + pc];
        fv[j] = *(const float4*)&vg[(size_t)(pr + j*16)*DM + pc];
    }
    #pragma unroll
    for (int j = 0; j < 4; j++) {
        int r = pr + j*16;
        uint4 uk; uk.x=tf32(fk[j].x); uk.y=tf32(fk[j].y); uk.z=tf32(fk[j].z); uk.w=tf32(fk[j].w);
        uint4 uv; uv.x=tf32(fv[j].x); uv.y=tf32(fv[j].y); uv.z=tf32(fv[j].z); uv.w=tf32(fv[j].w);
        *(uint4*)&Kb[r*KST + pc] = uk;
        *(uint4*)&Vb[r*VST + pc] = uv;
    }
    __syncthreads();

    int srcA = (lane & ~3) | (tg >> 1);
    int srcB = srcA + 2;

    for (int kt = 0; kt < NT_KEYS; kt++) {
        int cur = kt & 1;
        uint32_t* Kc = Kb + cur*64*KST;
        uint32_t* Vc = Vb + cur*64*VST;
        if (kt + 1 < NT_KEYS) {
            size_t base = (size_t)(kt+1)*64;
            #pragma unroll
            for (int j = 0; j < 4; j++) {
                fk[j] = *(const float4*)&kg[(base + pr + j*16)*DM + pc];
                fv[j] = *(const float4*)&vg[(base + pr + j*16)*DM + pc];
            }
        }

        // ---- S = Q K^T ----
        float c[2][8][4];
        #pragma unroll
        for (int mt=0;mt<2;mt++)
            #pragma unroll
            for (int nt=0;nt<8;nt++)
                #pragma unroll
                for (int q=0;q<4;q++) c[mt][nt][q]=0.f;
        #pragma unroll
        for (int kc = 0; kc < 4; kc++) {
            uint32_t bk[8][2];
            #pragma unroll
            for (int nt = 0; nt < 8; nt++) {
                bk[nt][0] = Kc[(nt*8+g)*KST + kc*8+tg  ];
                bk[nt][1] = Kc[(nt*8+g)*KST + kc*8+tg+4];
            }
            #pragma unroll
            for (int mt = 0; mt < 2; mt++)
                #pragma unroll
                for (int nt = 0; nt < 8; nt++)
                    mma8(c[mt][nt], aQ[mt][kc], bk[nt]);
        }

        // ---- online softmax ----
        #pragma unroll
        for (int mt = 0; mt < 2; mt++)
            #pragma unroll
            for (int hi = 0; hi < 2; hi++) {
                float tm = -1e30f;
                #pragma unroll
                for (int nt = 0; nt < 8; nt++) {
                    tm = fmaxf(tm, c[mt][nt][hi*2]);
                    tm = fmaxf(tm, c[mt][nt][hi*2+1]);
                }
                tm = fmaxf(tm, __shfl_xor_sync(0xffffffffu, tm, 1));
                tm = fmaxf(tm, __shfl_xor_sync(0xffffffffu, tm, 2));
                float mn = fmaxf(m[mt][hi], tm);
                float corr = __expf(m[mt][hi] - mn);
                m[mt][hi] = mn;
                lsum[mt][hi] *= corr;
                #pragma unroll
                for (int nt = 0; nt < 4; nt++) {
                    O[mt][nt][hi*2]   *= corr;
                    O[mt][nt][hi*2+1] *= corr;
                }
                float ls = 0.f;
                #pragma unroll
                for (int nt = 0; nt < 8; nt++) {
                    float p0 = __expf(c[mt][nt][hi*2]   - mn);
                    float p1 = __expf(c[mt][nt][hi*2+1] - mn);
                    c[mt][nt][hi*2]   = p0;
                    c[mt][nt][hi*2+1] = p1;
                    ls += p0 + p1;
                }
                lsum[mt][hi] += ls;
            }

        // ---- O += P V ----
        #pragma unroll
        for (int kc = 0; kc < 8; kc++) {
            uint32_t bv[4][2];
            #pragma unroll
            for (int nt = 0; nt < 4; nt++) {
                bv[nt][0] = Vc[(kc*8+tg  )*VST + nt*8+g];
                bv[nt][1] = Vc[(kc*8+tg+4)*VST + nt*8+g];
            }
            #pragma unroll
            for (int mt = 0; mt < 2; mt++) {
                float x0 = __shfl_sync(0xffffffffu, c[mt][kc][0], srcA);
                float x1 = __shfl_sync(0xffffffffu, c[mt][kc][1], srcA);
                float x2 = __shfl_sync(0xffffffffu, c[mt][kc][2], srcA);
                float x3 = __shfl_sync(0xffffffffu, c[mt][kc][3], srcA);
                float y0 = __shfl_sync(0xffffffffu, c[mt][kc][0], srcB);
                float y1 = __shfl_sync(0xffffffffu, c[mt][kc][1], srcB);
                float y2 = __shfl_sync(0xffffffffu, c[mt][kc][2], srcB);
                float y3 = __shfl_sync(0xffffffffu, c[mt][kc][3], srcB);
                uint32_t aP[4];
                aP[0] = tf32((tg & 1) ? x1 : x0);
                aP[1] = tf32((tg & 1) ? x3 : x2);
                aP[2] = tf32((tg & 1) ? y1 : y0);
                aP[3] = tf32((tg & 1) ? y3 : y2);
                #pragma unroll
                for (int nt = 0; nt < 4; nt++)
                    mma8(O[mt][nt], aP, bv[nt]);
            }
        }

        if (kt + 1 < NT_KEYS) {
            uint32_t* Kn = Kb + ((kt+1)&1)*64*KST;
            uint32_t* Vn = Vb + ((kt+1)&1)*64*VST;
            #pragma unroll
            for (int j = 0; j < 4; j++) {
                int r = pr + j*16;
                uint4 uk; uk.x=tf32(fk[j].x); uk.y=tf32(fk[j].y); uk.z=tf32(fk[j].z); uk.w=tf32(fk[j].w);
                uint4 uv; uv.x=tf32(fv[j].x); uv.y=tf32(fv[j].y); uv.z=tf32(fv[j].z); uv.w=tf32(fv[j].w);
                *(uint4*)&Kn[r*KST + pc] = uk;
                *(uint4*)&Vn[r*VST + pc] = uv;
            }
        }
        __syncthreads();
    }

    // ---- finalize & write ----
    #pragma unroll
    for (int mt = 0; mt < 2; mt++)
        #pragma unroll
        for (int hi = 0; hi < 2; hi++) {
            float l = lsum[mt][hi];
            l += __shfl_xor_sync(0xffffffffu, l, 1);
            l += __shfl_xor_sync(0xffffffffu, l, 2);
            float inv = 1.f / l;
            int qrow = qt*128 + w*32 + mt*16 + g + hi*8;
            float* op = &g_attn[((size_t)(b*SEQ + qrow))*DM + h*HD];
            #pragma unroll
            for (int nt = 0; nt < 4; nt++) {
                float2 o;
                o.x = O[mt][nt][hi*2]   * inv;
                o.y = O[mt][nt][hi*2+1] * inv;
                *(float2*)&op[nt*8 + 2*tg] = o;
            }
        }
}

extern "C" void kernel_launch(void* const* d_in, const int* in_sizes, int n_in,
                              void* d_out, int out_size) {
    const float* x  = (const float*)d_in[0];
    const float* Wq = (const float*)d_in[1];
    const float* bq = (const float*)d_in[2];
    const float* Wk = (const float*)d_in[3];
    const float* bk = (const float*)d_in[4];
    const float* Wv = (const float*)d_in[5];
    const float* bv = (const float*)d_in[6];
    const float* Wo = (const float*)d_in[7];
    const float* bo = (const float*)d_in[8];
    const float* W1 = (const float*)d_in[9];
    const float* b1 = (const float*)d_in[10];
    const float* W2 = (const float*)d_in[11];
    const float* b2 = (const float*)d_in[12];
    float* out = (float*)d_out;

    float *xn1, *q, *k, *v, *attn, *xskip, *xn2, *h1;
    cudaGetSymbolAddress((void**)&xn1,  g_xn1);
    cudaGetSymbolAddress((void**)&q,    g_q);
    cudaGetSymbolAddress((void**)&k,    g_k);
    cudaGetSymbolAddress((void**)&v,    g_v);
    cudaGetSymbolAddress((void**)&attn, g_attn);
    cudaGetSymbolAddress((void**)&xskip,g_xskip);
    cudaGetSymbolAddress((void**)&xn2,  g_xn2);
    cudaGetSymbolAddress((void**)&h1,   g_h1);

    dim3 gD (DM/256,  MROWS/64);    // (1,128)
    dim3 gF (DFF/256, MROWS/64);    // (4,128)

    ln_kernel<<<MROWS, 256>>>(x, xn1);
    mma_gemm<0><<<gD, 256>>>(xn1, Wq, bq, nullptr, q, MROWS, DM, DM);
    mma_gemm<0><<<gD, 256>>>(xn1, Wk, bk, nullptr, k, MROWS, DM, DM);
    mma_gemm<0><<<gD, 256>>>(xn1, Wv, bv, nullptr, v, MROWS, DM, DM);
    attn_mma<<<dim3(SEQ/128, BB*NH), 128>>>();
    mma_gemm<1><<<gD, 256>>>(attn, Wo, bo, x, xskip, MROWS, DM, DM);
    ln_kernel<<<MROWS, 256>>>(xskip, xn2);
    mma_gemm<2><<<gF, 256>>>(xn2, W1, b1, nullptr, h1, MROWS, DFF, DM);
    mma_gemm<3><<<gD, 256>>>(h1, W2, b2, xskip, out, MROWS, DM, DFF);
}

// round 6
// speedup vs baseline: 4.6218x; 1.2927x over previous
#include <cuda_runtime.h>
#include <cuda_fp16.h>
#include <math.h>
#include <stdint.h>
#include <string.h>

#define BB 2
#define SEQ 4096
#define DM 256
#define NH 8
#define HD 32
#define DFF 1024
#define MROWS (BB*SEQ)   // 8192

// ---- scratch (device globals; no allocation allowed) ----
__device__ float g_xn1 [MROWS*DM];
__device__ float g_q   [MROWS*DM];
__device__ float g_k   [MROWS*DM];
__device__ float g_v   [MROWS*DM];
__device__ float g_attn[MROWS*DM];
__device__ float g_xskip[MROWS*DM];
__device__ float g_xn2 [MROWS*DM];
__device__ float g_h1  [MROWS*DFF];

__device__ __forceinline__ uint32_t tf32(float x){ uint32_t r; asm("cvt.rna.tf32.f32 %0,%1;":"=r"(r):"f"(x)); return r; }

__device__ __forceinline__ void mma8(float c[4], const uint32_t a[4], const uint32_t b[2]) {
    asm volatile(
        "mma.sync.aligned.m16n8k8.row.col.f32.tf32.tf32.f32 "
        "{%0,%1,%2,%3}, {%4,%5,%6,%7}, {%8,%9}, {%0,%1,%2,%3};"
        : "+f"(c[0]), "+f"(c[1]), "+f"(c[2]), "+f"(c[3])
        : "r"(a[0]), "r"(a[1]), "r"(a[2]), "r"(a[3]), "r"(b[0]), "r"(b[1]));
}

__device__ __forceinline__ void mma16h(float c[4], const uint32_t a[4], const uint32_t b[2]) {
    asm volatile(
        "mma.sync.aligned.m16n8k16.row.col.f32.f16.f16.f32 "
        "{%0,%1,%2,%3}, {%4,%5,%6,%7}, {%8,%9}, {%0,%1,%2,%3};"
        : "+f"(c[0]), "+f"(c[1]), "+f"(c[2]), "+f"(c[3])
        : "r"(a[0]), "r"(a[1]), "r"(a[2]), "r"(a[3]), "r"(b[0]), "r"(b[1]));
}

__device__ __forceinline__ uint32_t pkh2(float lo, float hi){
    __half2 h = __floats2half2_rn(lo, hi);
    uint32_t r; memcpy(&r, &h, 4); return r;
}

__device__ __forceinline__ void ldmx2t(uint32_t &r0, uint32_t &r1, uint32_t saddr){
    asm volatile("ldmatrix.sync.aligned.m8n8.x2.trans.shared.b16 {%0,%1}, [%2];"
                 : "=r"(r0), "=r"(r1) : "r"(saddr));
}

// ---------------- LayerNorm ----------------
__global__ __launch_bounds__(256)
void ln_kernel(const float* __restrict__ x, float* __restrict__ y) {
    int row = blockIdx.x;
    int tid = threadIdx.x;
    float v = x[row*DM + tid];
    float s = v, s2 = v*v;
    #pragma unroll
    for (int o = 16; o; o >>= 1) {
        s  += __shfl_xor_sync(0xffffffffu, s,  o);
        s2 += __shfl_xor_sync(0xffffffffu, s2, o);
    }
    __shared__ float ss[8], ss2[8];
    int w = tid >> 5, l = tid & 31;
    if (l == 0) { ss[w] = s; ss2[w] = s2; }
    __syncthreads();
    float tot = 0.f, tot2 = 0.f;
    #pragma unroll
    for (int i = 0; i < 8; i++) { tot += ss[i]; tot2 += ss2[i]; }
    float m   = tot * (1.0f/DM);
    float var = tot2 * (1.0f/DM) - m*m;
    float inv = 1.0f / (sqrtf(fmaxf(var, 0.f)) + 1e-6f);
    y[row*DM + tid] = (v - m) * inv;
}

// ---------------- tf32 tensor-core GEMM body ----------------
template<int EP>
__device__ __forceinline__
void gemm_body(const float* __restrict__ A, const float* __restrict__ Wm,
               const float* __restrict__ bias, const float* __restrict__ res,
               float* __restrict__ out, int M, int N, int K,
               int bx, int by) {
    __shared__ uint32_t As[64][20];
    __shared__ uint32_t Bs[16][264];
    int tid = threadIdx.x, lane = tid & 31, warp = tid >> 5;
    int wm = warp & 1, wn = warp >> 1;
    int m0 = by * 64, n0 = bx * 256;
    int g = lane >> 2, tg = lane & 3;
    float c[2][8][4];
    #pragma unroll
    for (int i=0;i<2;i++)
        #pragma unroll
        for(int j=0;j<8;j++)
            #pragma unroll
            for(int q=0;q<4;q++) c[i][j][q]=0.f;

    for (int k0 = 0; k0 < K; k0 += 16) {
        {
            int r = tid >> 2, c4 = (tid & 3) * 4;
            float4 v = *(const float4*)&A[(size_t)(m0+r)*K + k0 + c4];
            uint4 u; u.x=tf32(v.x); u.y=tf32(v.y); u.z=tf32(v.z); u.w=tf32(v.w);
            *(uint4*)&As[r][c4] = u;
        }
        #pragma unroll
        for (int i = 0; i < 4; i++) {
            int idx = tid + i*256;
            int r = idx >> 6, cc = (idx & 63) * 4;
            float4 v = *(const float4*)&Wm[(size_t)(k0+r)*N + n0 + cc];
            uint4 u; u.x=tf32(v.x); u.y=tf32(v.y); u.z=tf32(v.z); u.w=tf32(v.w);
            *(uint4*)&Bs[r][cc] = u;
        }
        __syncthreads();
        #pragma unroll
        for (int ks = 0; ks < 2; ks++) {
            int kb = ks * 8;
            uint32_t a[2][4];
            #pragma unroll
            for (int mt = 0; mt < 2; mt++) {
                int r = wm*32 + mt*16;
                a[mt][0] = As[r+g  ][kb+tg  ];
                a[mt][1] = As[r+g+8][kb+tg  ];
                a[mt][2] = As[r+g  ][kb+tg+4];
                a[mt][3] = As[r+g+8][kb+tg+4];
            }
            uint32_t b[8][2];
            #pragma unroll
            for (int nt = 0; nt < 8; nt++) {
                int col = wn*64 + nt*8 + g;
                b[nt][0] = Bs[kb+tg  ][col];
                b[nt][1] = Bs[kb+tg+4][col];
            }
            #pragma unroll
            for (int mt = 0; mt < 2; mt++)
                #pragma unroll
                for (int nt = 0; nt < 8; nt++)
                    mma8(c[mt][nt], a[mt], b[nt]);
        }
        __syncthreads();
    }
    #pragma unroll
    for (int mt = 0; mt < 2; mt++) {
        #pragma unroll
        for (int nt = 0; nt < 8; nt++) {
            int col = n0 + wn*64 + nt*8 + 2*tg;
            float2 bv = *(const float2*)&bias[col];
            #pragma unroll
            for (int half = 0; half < 2; half++) {
                int row = m0 + wm*32 + mt*16 + g + half*8;
                float v0 = c[mt][nt][half*2+0] + bv.x;
                float v1 = c[mt][nt][half*2+1] + bv.y;
                if (EP == 1 || EP == 3) {
                    float2 rv = *(const float2*)&res[(size_t)row*N + col];
                    v0 += rv.x; v1 += rv.y;
                }
                if (EP == 2) {
                    float i0 = 0.7978845608028654f * (v0 + 0.044715f*v0*v0*v0);
                    float i1 = 0.7978845608028654f * (v1 + 0.044715f*v1*v1*v1);
                    v0 = 0.5f * v0 * (1.0f + tanhf(i0));
                    v1 = 0.5f * v1 * (1.0f + tanhf(i1));
                }
                float2 o; o.x = v0; o.y = v1;
                *(float2*)&out[(size_t)row*N + col] = o;
            }
        }
    }
}

template<int EP>
__global__ __launch_bounds__(256)
void mma_gemm(const float* __restrict__ A, const float* __restrict__ Wm,
              const float* __restrict__ bias, const float* __restrict__ res,
              float* __restrict__ out, int M, int N, int K) {
    gemm_body<EP>(A, Wm, bias, res, out, M, N, K, blockIdx.x, blockIdx.y);
}

// fused QKV: blockIdx.z selects (W, bias, out)
__global__ __launch_bounds__(256)
void qkv_gemm(const float* __restrict__ A,
              const float* __restrict__ Wq, const float* __restrict__ bq, float* __restrict__ oq,
              const float* __restrict__ Wk, const float* __restrict__ bk, float* __restrict__ ok,
              const float* __restrict__ Wv, const float* __restrict__ bv, float* __restrict__ ov) {
    const float* W; const float* bi; float* o;
    if (blockIdx.z == 0)      { W = Wq; bi = bq; o = oq; }
    else if (blockIdx.z == 1) { W = Wk; bi = bk; o = ok; }
    else                      { W = Wv; bi = bv; o = ov; }
    gemm_body<0>(A, W, bi, nullptr, o, MROWS, DM, DM, blockIdx.x, blockIdx.y);
}

// ---------------- Tensor-core flash attention (S: tf32, PV: fp16) ----------------
#define KST 36            // K tile row stride (b32 units)
#define VSTH 40           // V tile row stride (halves)
#define NT_KEYS (SEQ/64)
#define KWORDS (2*64*KST)             // 4608 b32
#define VWORDS (2*64*VSTH/2)          // 2560 b32 (half units /2)

__global__ __launch_bounds__(128)
void attn_mma() {
    __shared__ __align__(16) uint32_t sraw[KWORDS + VWORDS];  // 28672 B
    float*    Qs = (float*)sraw;                 // [128][33] phase 1 only (16896 B)
    uint32_t* Kb = sraw;                         // [2][64][KST] tf32
    __half*   Vb = (__half*)(sraw + KWORDS);     // [2][64][VSTH] fp16

    int qt = blockIdx.x;
    int bh = blockIdx.y;
    int b = bh >> 3, h = bh & 7;
    int tid = threadIdx.x, lane = tid & 31, w = tid >> 5;
    int g = lane >> 2, tg = lane & 3;

    const float scale = 0.17677669529663687f;    // 1/sqrt(32)
    const float* qg = &g_q[((size_t)(b*SEQ + qt*128))*DM + h*HD];
    const float* kg = &g_k[(size_t)b*SEQ*DM + h*HD];
    const float* vg = &g_v[(size_t)b*SEQ*DM + h*HD];

    // ---- load Q tile (scaled), build persistent A fragments ----
    #pragma unroll
    for (int i = 0; i < 8; i++) {
        int e = tid + i*128;
        int r = e >> 3, c4 = (e & 7)*4;
        float4 v = *(const float4*)&qg[(size_t)r*DM + c4];
        Qs[r*33+c4+0]=v.x*scale; Qs[r*33+c4+1]=v.y*scale;
        Qs[r*33+c4+2]=v.z*scale; Qs[r*33+c4+3]=v.w*scale;
    }
    __syncthreads();
    uint32_t aQ[2][4][4];
    #pragma unroll
    for (int mt = 0; mt < 2; mt++)
        #pragma unroll
        for (int kc = 0; kc < 4; kc++) {
            int r = w*32 + mt*16;
            aQ[mt][kc][0] = tf32(Qs[(r+g  )*33 + kc*8+tg  ]);
            aQ[mt][kc][1] = tf32(Qs[(r+g+8)*33 + kc*8+tg  ]);
            aQ[mt][kc][2] = tf32(Qs[(r+g  )*33 + kc*8+tg+4]);
            aQ[mt][kc][3] = tf32(Qs[(r+g+8)*33 + kc*8+tg+4]);
        }
    __syncthreads();   // Qs region about to be reused as K/V buffers

    float O[2][4][4];
    #pragma unroll
    for (int mt=0;mt<2;mt++)
        #pragma unroll
        for (int nt=0;nt<4;nt++)
            #pragma unroll
            for (int q=0;q<4;q++) O[mt][nt][q]=0.f;
    float m[2][2] = {{-1e30f,-1e30f},{-1e30f,-1e30f}};
    float lsum[2][2] = {{0.f,0.f},{0.f,0.f}};

    // loader: 64x32 tile = 512 float4; 128 threads x 4 float4 each
    int pr = tid >> 3, pc = (tid & 7)*4;
    float4 fk[4], fv[4];
    #pragma unroll
    for (int j = 0; j < 4; j++) {
        fk[j] = *(const float4*)&kg[(size_t)(pr + j*16)*DM + pc];
        fv[j] = *(const float4*)&vg[(size_t)(pr + j*16)*DM + pc];
    }
    #pragma unroll
    for (int j = 0; j < 4; j++) {
        int r = pr + j*16;
        uint4 uk; uk.x=tf32(fk[j].x); uk.y=tf32(fk[j].y); uk.z=tf32(fk[j].z); uk.w=tf32(fk[j].w);
        *(uint4*)&Kb[r*KST + pc] = uk;
        uint32_t h0 = pkh2(fv[j].x, fv[j].y), h1 = pkh2(fv[j].z, fv[j].w);
        uint2 hv; hv.x = h0; hv.y = h1;
        *(uint2*)&Vb[r*VSTH + pc] = hv;
    }
    __syncthreads();

    int ldrow = lane & 15;   // ldmatrix source row within 16-key chunk

    for (int kt = 0; kt < NT_KEYS; kt++) {
        int cur = kt & 1;
        uint32_t* Kc = Kb + cur*64*KST;
        __half*   Vc = Vb + cur*64*VSTH;
        uint32_t vsb = (uint32_t)__cvta_generic_to_shared(Vc) + (uint32_t)(ldrow*VSTH*2);

        if (kt + 1 < NT_KEYS) {
            size_t base = (size_t)(kt+1)*64;
            #pragma unroll
            for (int j = 0; j < 4; j++) {
                fk[j] = *(const float4*)&kg[(base + pr + j*16)*DM + pc];
                fv[j] = *(const float4*)&vg[(base + pr + j*16)*DM + pc];
            }
        }

        // ---- S = Q K^T (tf32) ----
        float c[2][8][4];
        #pragma unroll
        for (int mt=0;mt<2;mt++)
            #pragma unroll
            for (int nt=0;nt<8;nt++)
                #pragma unroll
                for (int q=0;q<4;q++) c[mt][nt][q]=0.f;
        #pragma unroll
        for (int kc = 0; kc < 4; kc++) {
            uint32_t bk[8][2];
            #pragma unroll
            for (int nt = 0; nt < 8; nt++) {
                bk[nt][0] = Kc[(nt*8+g)*KST + kc*8+tg  ];
                bk[nt][1] = Kc[(nt*8+g)*KST + kc*8+tg+4];
            }
            #pragma unroll
            for (int mt = 0; mt < 2; mt++)
                #pragma unroll
                for (int nt = 0; nt < 8; nt++)
                    mma8(c[mt][nt], aQ[mt][kc], bk[nt]);
        }

        // ---- online softmax ----
        #pragma unroll
        for (int mt = 0; mt < 2; mt++)
            #pragma unroll
            for (int hi = 0; hi < 2; hi++) {
                float tm = -1e30f;
                #pragma unroll
                for (int nt = 0; nt < 8; nt++) {
                    tm = fmaxf(tm, c[mt][nt][hi*2]);
                    tm = fmaxf(tm, c[mt][nt][hi*2+1]);
                }
                tm = fmaxf(tm, __shfl_xor_sync(0xffffffffu, tm, 1));
                tm = fmaxf(tm, __shfl_xor_sync(0xffffffffu, tm, 2));
                float mn = fmaxf(m[mt][hi], tm);
                float corr = __expf(m[mt][hi] - mn);
                m[mt][hi] = mn;
                lsum[mt][hi] *= corr;
                #pragma unroll
                for (int nt = 0; nt < 4; nt++) {
                    O[mt][nt][hi*2]   *= corr;
                    O[mt][nt][hi*2+1] *= corr;
                }
                float ls = 0.f;
                #pragma unroll
                for (int nt = 0; nt < 8; nt++) {
                    float p0 = __expf(c[mt][nt][hi*2]   - mn);
                    float p1 = __expf(c[mt][nt][hi*2+1] - mn);
                    c[mt][nt][hi*2]   = p0;
                    c[mt][nt][hi*2+1] = p1;
                    ls += p0 + p1;
                }
                lsum[mt][hi] += ls;
            }

        // ---- O += P V  (fp16 mma, P packed from C frags, V via ldmatrix.trans) ----
        #pragma unroll
        for (int kc = 0; kc < 4; kc++) {       // 16-key chunks
            uint32_t aP[2][4];
            #pragma unroll
            for (int mt = 0; mt < 2; mt++) {
                aP[mt][0] = pkh2(c[mt][2*kc  ][0], c[mt][2*kc  ][1]);
                aP[mt][1] = pkh2(c[mt][2*kc  ][2], c[mt][2*kc  ][3]);
                aP[mt][2] = pkh2(c[mt][2*kc+1][0], c[mt][2*kc+1][1]);
                aP[mt][3] = pkh2(c[mt][2*kc+1][2], c[mt][2*kc+1][3]);
            }
            #pragma unroll
            for (int nt = 0; nt < 4; nt++) {
                uint32_t bv[2];
                uint32_t addr = vsb + (uint32_t)(kc*16*VSTH*2 + nt*8*2);
                ldmx2t(bv[0], bv[1], addr);
                mma16h(O[0][nt], aP[0], bv);
                mma16h(O[1][nt], aP[1], bv);
            }
        }

        if (kt + 1 < NT_KEYS) {
            int nxt = (kt+1) & 1;
            uint32_t* Kn = Kb + nxt*64*KST;
            __half*   Vn = Vb + nxt*64*VSTH;
            #pragma unroll
            for (int j = 0; j < 4; j++) {
                int r = pr + j*16;
                uint4 uk; uk.x=tf32(fk[j].x); uk.y=tf32(fk[j].y); uk.z=tf32(fk[j].z); uk.w=tf32(fk[j].w);
                *(uint4*)&Kn[r*KST + pc] = uk;
                uint32_t h0 = pkh2(fv[j].x, fv[j].y), h1 = pkh2(fv[j].z, fv[j].w);
                uint2 hv; hv.x = h0; hv.y = h1;
                *(uint2*)&Vn[r*VSTH + pc] = hv;
            }
        }
        __syncthreads();
    }

    // ---- finalize & write ----
    #pragma unroll
    for (int mt = 0; mt < 2; mt++)
        #pragma unroll
        for (int hi = 0; hi < 2; hi++) {
            float l = lsum[mt][hi];
            l += __shfl_xor_sync(0xffffffffu, l, 1);
            l += __shfl_xor_sync(0xffffffffu, l, 2);
            float inv = 1.f / l;
            int qrow = qt*128 + w*32 + mt*16 + g + hi*8;
            float* op = &g_attn[((size_t)(b*SEQ + qrow))*DM + h*HD];
            #pragma unroll
            for (int nt = 0; nt < 4; nt++) {
                float2 o;
                o.x = O[mt][nt][hi*2]   * inv;
                o.y = O[mt][nt][hi*2+1] * inv;
                *(float2*)&op[nt*8 + 2*tg] = o;
            }
        }
}

extern "C" void kernel_launch(void* const* d_in, const int* in_sizes, int n_in,
                              void* d_out, int out_size) {
    const float* x  = (const float*)d_in[0];
    const float* Wq = (const float*)d_in[1];
    const float* bq = (const float*)d_in[2];
    const float* Wk = (const float*)d_in[3];
    const float* bk = (const float*)d_in[4];
    const float* Wv = (const float*)d_in[5];
    const float* bv = (const float*)d_in[6];
    const float* Wo = (const float*)d_in[7];
    const float* bo = (const float*)d_in[8];
    const float* W1 = (const float*)d_in[9];
    const float* b1 = (const float*)d_in[10];
    const float* W2 = (const float*)d_in[11];
    const float* b2 = (const float*)d_in[12];
    float* out = (float*)d_out;

    float *xn1, *q, *k, *v, *attn, *xskip, *xn2, *h1;
    cudaGetSymbolAddress((void**)&xn1,  g_xn1);
    cudaGetSymbolAddress((void**)&q,    g_q);
    cudaGetSymbolAddress((void**)&k,    g_k);
    cudaGetSymbolAddress((void**)&v,    g_v);
    cudaGetSymbolAddress((void**)&attn, g_attn);
    cudaGetSymbolAddress((void**)&xskip,g_xskip);
    cudaGetSymbolAddress((void**)&xn2,  g_xn2);
    cudaGetSymbolAddress((void**)&h1,   g_h1);

    dim3 gD (DM/256,  MROWS/64);       // (1,128)
    dim3 gQKV(DM/256, MROWS/64, 3);    // (1,128,3)
    dim3 gF (DFF/256, MROWS/64);       // (4,128)

    ln_kernel<<<MROWS, 256>>>(x, xn1);
    qkv_gemm<<<gQKV, 256>>>(xn1, Wq, bq, q, Wk, bk, k, Wv, bv, v);
    attn_mma<<<dim3(SEQ/128, BB*NH), 128>>>();
    mma_gemm<1><<<gD, 256>>>(attn, Wo, bo, x, xskip, MROWS, DM, DM);
    ln_kernel<<<MROWS, 256>>>(xskip, xn2);
    mma_gemm<2><<<gF, 256>>>(xn2, W1, b1, nullptr, h1, MROWS, DFF, DM);
    mma_gemm<3><<<gD, 256>>>(h1, W2, b2, xskip, out, MROWS, DM, DFF);
}

// round 7
// speedup vs baseline: 5.5374x; 1.1981x over previous
#include <cuda_runtime.h>
#include <cuda_fp16.h>
#include <math.h>
#include <stdint.h>
#include <string.h>

#define BB 2
#define SEQ 4096
#define DM 256
#define NH 8
#define HD 32
#define DFF 1024
#define MROWS (BB*SEQ)   // 8192

// ---- scratch (device globals; no allocation allowed) ----
__device__ float g_xn1 [MROWS*DM];
__device__ float g_q   [MROWS*DM];
__device__ float g_k   [MROWS*DM];
__device__ float g_v   [MROWS*DM];
__device__ float g_attn[MROWS*DM];
__device__ float g_xskip[MROWS*DM];
__device__ float g_xn2 [MROWS*DM];
__device__ float g_h1  [MROWS*DFF];

__device__ __forceinline__ uint32_t tf32(float x){ uint32_t r; asm("cvt.rna.tf32.f32 %0,%1;":"=r"(r):"f"(x)); return r; }

__device__ __forceinline__ void mma8(float c[4], const uint32_t a[4], const uint32_t b[2]) {
    asm volatile(
        "mma.sync.aligned.m16n8k8.row.col.f32.tf32.tf32.f32 "
        "{%0,%1,%2,%3}, {%4,%5,%6,%7}, {%8,%9}, {%0,%1,%2,%3};"
        : "+f"(c[0]), "+f"(c[1]), "+f"(c[2]), "+f"(c[3])
        : "r"(a[0]), "r"(a[1]), "r"(a[2]), "r"(a[3]), "r"(b[0]), "r"(b[1]));
}

__device__ __forceinline__ void mma16h(float c[4], const uint32_t a[4], const uint32_t b[2]) {
    asm volatile(
        "mma.sync.aligned.m16n8k16.row.col.f32.f16.f16.f32 "
        "{%0,%1,%2,%3}, {%4,%5,%6,%7}, {%8,%9}, {%0,%1,%2,%3};"
        : "+f"(c[0]), "+f"(c[1]), "+f"(c[2]), "+f"(c[3])
        : "r"(a[0]), "r"(a[1]), "r"(a[2]), "r"(a[3]), "r"(b[0]), "r"(b[1]));
}

__device__ __forceinline__ uint32_t pkh2(float lo, float hi){
    __half2 h = __floats2half2_rn(lo, hi);
    uint32_t r; memcpy(&r, &h, 4); return r;
}

__device__ __forceinline__ void ldmx2t(uint32_t &r0, uint32_t &r1, uint32_t saddr){
    asm volatile("ldmatrix.sync.aligned.m8n8.x2.trans.shared.b16 {%0,%1}, [%2];"
                 : "=r"(r0), "=r"(r1) : "r"(saddr));
}

// ---------------- LayerNorm: one warp per row ----------------
__global__ __launch_bounds__(256)
void ln_kernel(const float* __restrict__ x, float* __restrict__ y) {
    int w = threadIdx.x >> 5, lane = threadIdx.x & 31;
    size_t row = (size_t)blockIdx.x*8 + w;
    const float* xr = &x[row*DM];
    float4 v0 = *(const float4*)&xr[lane*4];
    float4 v1 = *(const float4*)&xr[128 + lane*4];
    float s  = v0.x+v0.y+v0.z+v0.w + v1.x+v1.y+v1.z+v1.w;
    float s2 = v0.x*v0.x+v0.y*v0.y+v0.z*v0.z+v0.w*v0.w
             + v1.x*v1.x+v1.y*v1.y+v1.z*v1.z+v1.w*v1.w;
    #pragma unroll
    for (int o = 16; o; o >>= 1) {
        s  += __shfl_xor_sync(0xffffffffu, s,  o);
        s2 += __shfl_xor_sync(0xffffffffu, s2, o);
    }
    float m   = s * (1.0f/DM);
    float var = s2 * (1.0f/DM) - m*m;
    float inv = 1.0f / (sqrtf(fmaxf(var, 0.f)) + 1e-6f);
    float* yr = &y[row*DM];
    float4 o0; o0.x=(v0.x-m)*inv; o0.y=(v0.y-m)*inv; o0.z=(v0.z-m)*inv; o0.w=(v0.w-m)*inv;
    float4 o1; o1.x=(v1.x-m)*inv; o1.y=(v1.y-m)*inv; o1.z=(v1.z-m)*inv; o1.w=(v1.w-m)*inv;
    *(float4*)&yr[lane*4]       = o0;
    *(float4*)&yr[128 + lane*4] = o1;
}

// ---------------- fp16 tensor-core GEMM ----------------
// Block 64x128, BK=16, 8 warps (2m x 4n), warp tile 32x32.
// As: [64 rows][kp stride 12] u32 (half2 k-pairs). Bs: [8 kp][col stride 136] u32.
#define AST 12
#define BST 136
template<int EP>
__device__ __forceinline__
void gemm_body(const float* __restrict__ A, const float* __restrict__ Wm,
               const float* __restrict__ bias, const float* __restrict__ res,
               float* __restrict__ out, int M, int N, int K,
               int bx, int by) {
    __shared__ uint32_t As[64*AST];
    __shared__ uint32_t Bs[8*BST];
    int tid = threadIdx.x, lane = tid & 31, warp = tid >> 5;
    int wm = warp & 1, wn = warp >> 1;              // 2m x 4n
    int m0 = by * 64, n0 = bx * 128;
    int g = lane >> 2, tg = lane & 3;
    float c[2][4][4];
    #pragma unroll
    for (int i=0;i<2;i++)
        #pragma unroll
        for(int j=0;j<4;j++)
            #pragma unroll
            for(int q=0;q<4;q++) c[i][j][q]=0.f;

    int ar = tid >> 2, ak = tid & 3;                 // A loader: row, k-quad
    int bkp = tid >> 5, bc = lane * 4;               // B loader: k-pair, col quad

    for (int k0 = 0; k0 < K; k0 += 16) {
        float4 av = *(const float4*)&A[(size_t)(m0+ar)*K + k0 + ak*4];
        uint2 au; au.x = pkh2(av.x, av.y); au.y = pkh2(av.z, av.w);
        *(uint2*)&As[ar*AST + ak*2] = au;

        float4 b0 = *(const float4*)&Wm[(size_t)(k0+2*bkp  )*N + n0 + bc];
        float4 b1 = *(const float4*)&Wm[(size_t)(k0+2*bkp+1)*N + n0 + bc];
        uint4 bu; bu.x = pkh2(b0.x, b1.x); bu.y = pkh2(b0.y, b1.y);
        bu.z = pkh2(b0.z, b1.z); bu.w = pkh2(b0.w, b1.w);
        *(uint4*)&Bs[bkp*BST + bc] = bu;
        __syncthreads();

        uint32_t a[2][4];
        #pragma unroll
        for (int mt = 0; mt < 2; mt++) {
            int r = wm*32 + mt*16;
            a[mt][0] = As[(r+g  )*AST + tg  ];
            a[mt][1] = As[(r+g+8)*AST + tg  ];
            a[mt][2] = As[(r+g  )*AST + tg+4];
            a[mt][3] = As[(r+g+8)*AST + tg+4];
        }
        uint32_t b[4][2];
        #pragma unroll
        for (int nt = 0; nt < 4; nt++) {
            int col = wn*32 + nt*8 + g;
            b[nt][0] = Bs[ tg   *BST + col];
            b[nt][1] = Bs[(tg+4)*BST + col];
        }
        #pragma unroll
        for (int mt = 0; mt < 2; mt++)
            #pragma unroll
            for (int nt = 0; nt < 4; nt++)
                mma16h(c[mt][nt], a[mt], b[nt]);
        __syncthreads();
    }
    #pragma unroll
    for (int mt = 0; mt < 2; mt++) {
        #pragma unroll
        for (int nt = 0; nt < 4; nt++) {
            int col = n0 + wn*32 + nt*8 + 2*tg;
            float2 bv = *(const float2*)&bias[col];
            #pragma unroll
            for (int half = 0; half < 2; half++) {
                int row = m0 + wm*32 + mt*16 + g + half*8;
                float v0 = c[mt][nt][half*2+0] + bv.x;
                float v1 = c[mt][nt][half*2+1] + bv.y;
                if (EP == 1 || EP == 3) {
                    float2 rv = *(const float2*)&res[(size_t)row*N + col];
                    v0 += rv.x; v1 += rv.y;
                }
                if (EP == 2) {
                    float i0 = 0.7978845608028654f * (v0 + 0.044715f*v0*v0*v0);
                    float i1 = 0.7978845608028654f * (v1 + 0.044715f*v1*v1*v1);
                    v0 = 0.5f * v0 * (1.0f + tanhf(i0));
                    v1 = 0.5f * v1 * (1.0f + tanhf(i1));
                }
                float2 o; o.x = v0; o.y = v1;
                *(float2*)&out[(size_t)row*N + col] = o;
            }
        }
    }
}

template<int EP>
__global__ __launch_bounds__(256)
void mma_gemm(const float* __restrict__ A, const float* __restrict__ Wm,
              const float* __restrict__ bias, const float* __restrict__ res,
              float* __restrict__ out, int M, int N, int K) {
    gemm_body<EP>(A, Wm, bias, res, out, M, N, K, blockIdx.x, blockIdx.y);
}

__global__ __launch_bounds__(256)
void qkv_gemm(const float* __restrict__ A,
              const float* __restrict__ Wq, const float* __restrict__ bq, float* __restrict__ oq,
              const float* __restrict__ Wk, const float* __restrict__ bk, float* __restrict__ ok,
              const float* __restrict__ Wv, const float* __restrict__ bv, float* __restrict__ ov) {
    const float* W; const float* bi; float* o;
    if (blockIdx.z == 0)      { W = Wq; bi = bq; o = oq; }
    else if (blockIdx.z == 1) { W = Wk; bi = bk; o = ok; }
    else                      { W = Wv; bi = bv; o = ov; }
    gemm_body<0>(A, W, bi, nullptr, o, MROWS, DM, DM, blockIdx.x, blockIdx.y);
}

// ---------------- Tensor-core flash attention (S: tf32, PV: fp16) ----------------
#define KST 36
#define VSTH 40
#define NT_KEYS (SEQ/64)
#define KWORDS (2*64*KST)
#define VWORDS (2*64*VSTH/2)

__global__ __launch_bounds__(128)
void attn_mma() {
    __shared__ __align__(16) uint32_t sraw[KWORDS + VWORDS];  // 28672 B
    float*    Qs = (float*)sraw;
    uint32_t* Kb = sraw;
    __half*   Vb = (__half*)(sraw + KWORDS);

    int qt = blockIdx.x;
    int bh = blockIdx.y;
    int b = bh >> 3, h = bh & 7;
    int tid = threadIdx.x, lane = tid & 31, w = tid >> 5;
    int g = lane >> 2, tg = lane & 3;

    const float scale = 0.17677669529663687f;
    const float* qg = &g_q[((size_t)(b*SEQ + qt*128))*DM + h*HD];
    const float* kg = &g_k[(size_t)b*SEQ*DM + h*HD];
    const float* vg = &g_v[(size_t)b*SEQ*DM + h*HD];

    #pragma unroll
    for (int i = 0; i < 8; i++) {
        int e = tid + i*128;
        int r = e >> 3, c4 = (e & 7)*4;
        float4 v = *(const float4*)&qg[(size_t)r*DM + c4];
        Qs[r*33+c4+0]=v.x*scale; Qs[r*33+c4+1]=v.y*scale;
        Qs[r*33+c4+2]=v.z*scale; Qs[r*33+c4+3]=v.w*scale;
    }
    __syncthreads();
    uint32_t aQ[2][4][4];
    #pragma unroll
    for (int mt = 0; mt < 2; mt++)
        #pragma unroll
        for (int kc = 0; kc < 4; kc++) {
            int r = w*32 + mt*16;
            aQ[mt][kc][0] = tf32(Qs[(r+g  )*33 + kc*8+tg  ]);
            aQ[mt][kc][1] = tf32(Qs[(r+g+8)*33 + kc*8+tg  ]);
            aQ[mt][kc][2] = tf32(Qs[(r+g  )*33 + kc*8+tg+4]);
            aQ[mt][kc][3] = tf32(Qs[(r+g+8)*33 + kc*8+tg+4]);
        }
    __syncthreads();

    float O[2][4][4];
    #pragma unroll
    for (int mt=0;mt<2;mt++)
        #pragma unroll
        for (int nt=0;nt<4;nt++)
            #pragma unroll
            for (int q=0;q<4;q++) O[mt][nt][q]=0.f;
    float m[2][2] = {{-1e30f,-1e30f},{-1e30f,-1e30f}};
    float lsum[2][2] = {{0.f,0.f},{0.f,0.f}};

    int pr = tid >> 3, pc = (tid & 7)*4;
    float4 fk[4], fv[4];
    #pragma unroll
    for (int j = 0; j < 4; j++) {
        fk[j] = *(const float4*)&kg[(size_t)(pr + j*16)*DM + pc];
        fv[j] = *(const float4*)&vg[(size_t)(pr + j*16)*DM + pc];
    }
    #pragma unroll
    for (int j = 0; j < 4; j++) {
        int r = pr + j*16;
        uint4 uk; uk.x=tf32(fk[j].x); uk.y=tf32(fk[j].y); uk.z=tf32(fk[j].z); uk.w=tf32(fk[j].w);
        *(uint4*)&Kb[r*KST + pc] = uk;
        uint32_t h0 = pkh2(fv[j].x, fv[j].y), h1 = pkh2(fv[j].z, fv[j].w);
        uint2 hv; hv.x = h0; hv.y = h1;
        *(uint2*)&Vb[r*VSTH + pc] = hv;
    }
    __syncthreads();

    int ldrow = lane & 15;

    for (int kt = 0; kt < NT_KEYS; kt++) {
        int cur = kt & 1;
        uint32_t* Kc = Kb + cur*64*KST;
        __half*   Vc = Vb + cur*64*VSTH;
        uint32_t vsb = (uint32_t)__cvta_generic_to_shared(Vc) + (uint32_t)(ldrow*VSTH*2);

        if (kt + 1 < NT_KEYS) {
            size_t base = (size_t)(kt+1)*64;
            #pragma unroll
            for (int j = 0; j < 4; j++) {
                fk[j] = *(const float4*)&kg[(base + pr + j*16)*DM + pc];
                fv[j] = *(const float4*)&vg[(base + pr + j*16)*DM + pc];
            }
        }

        float c[2][8][4];
        #pragma unroll
        for (int mt=0;mt<2;mt++)
            #pragma unroll
            for (int nt=0;nt<8;nt++)
                #pragma unroll
                for (int q=0;q<4;q++) c[mt][nt][q]=0.f;
        #pragma unroll
        for (int kc = 0; kc < 4; kc++) {
            uint32_t bk[8][2];
            #pragma unroll
            for (int nt = 0; nt < 8; nt++) {
                bk[nt][0] = Kc[(nt*8+g)*KST + kc*8+tg  ];
                bk[nt][1] = Kc[(nt*8+g)*KST + kc*8+tg+4];
            }
            #pragma unroll
            for (int mt = 0; mt < 2; mt++)
                #pragma unroll
                for (int nt = 0; nt < 8; nt++)
                    mma8(c[mt][nt], aQ[mt][kc], bk[nt]);
        }

        #pragma unroll
        for (int mt = 0; mt < 2; mt++)
            #pragma unroll
            for (int hi = 0; hi < 2; hi++) {
                float tm = -1e30f;
                #pragma unroll
                for (int nt = 0; nt < 8; nt++) {
                    tm = fmaxf(tm, c[mt][nt][hi*2]);
                    tm = fmaxf(tm, c[mt][nt][hi*2+1]);
                }
                tm = fmaxf(tm, __shfl_xor_sync(0xffffffffu, tm, 1));
                tm = fmaxf(tm, __shfl_xor_sync(0xffffffffu, tm, 2));
                float mn = fmaxf(m[mt][hi], tm);
                float corr = __expf(m[mt][hi] - mn);
                m[mt][hi] = mn;
                lsum[mt][hi] *= corr;
                #pragma unroll
                for (int nt = 0; nt < 4; nt++) {
                    O[mt][nt][hi*2]   *= corr;
                    O[mt][nt][hi*2+1] *= corr;
                }
                float ls = 0.f;
                #pragma unroll
                for (int nt = 0; nt < 8; nt++) {
                    float p0 = __expf(c[mt][nt][hi*2]   - mn);
                    float p1 = __expf(c[mt][nt][hi*2+1] - mn);
                    c[mt][nt][hi*2]   = p0;
                    c[mt][nt][hi*2+1] = p1;
                    ls += p0 + p1;
                }
                lsum[mt][hi] += ls;
            }

        #pragma unroll
        for (int kc = 0; kc < 4; kc++) {
            uint32_t aP[2][4];
            #pragma unroll
            for (int mt = 0; mt < 2; mt++) {
                aP[mt][0] = pkh2(c[mt][2*kc  ][0], c[mt][2*kc  ][1]);
                aP[mt][1] = pkh2(c[mt][2*kc  ][2], c[mt][2*kc  ][3]);
                aP[mt][2] = pkh2(c[mt][2*kc+1][0], c[mt][2*kc+1][1]);
                aP[mt][3] = pkh2(c[mt][2*kc+1][2], c[mt][2*kc+1][3]);
            }
            #pragma unroll
            for (int nt = 0; nt < 4; nt++) {
                uint32_t bv[2];
                uint32_t addr = vsb + (uint32_t)(kc*16*VSTH*2 + nt*8*2);
                ldmx2t(bv[0], bv[1], addr);
                mma16h(O[0][nt], aP[0], bv);
                mma16h(O[1][nt], aP[1], bv);
            }
        }

        if (kt + 1 < NT_KEYS) {
            int nxt = (kt+1) & 1;
            uint32_t* Kn = Kb + nxt*64*KST;
            __half*   Vn = Vb + nxt*64*VSTH;
            #pragma unroll
            for (int j = 0; j < 4; j++) {
                int r = pr + j*16;
                uint4 uk; uk.x=tf32(fk[j].x); uk.y=tf32(fk[j].y); uk.z=tf32(fk[j].z); uk.w=tf32(fk[j].w);
                *(uint4*)&Kn[r*KST + pc] = uk;
                uint32_t h0 = pkh2(fv[j].x, fv[j].y), h1 = pkh2(fv[j].z, fv[j].w);
                uint2 hv; hv.x = h0; hv.y = h1;
                *(uint2*)&Vn[r*VSTH + pc] = hv;
            }
        }
        __syncthreads();
    }

    #pragma unroll
    for (int mt = 0; mt < 2; mt++)
        #pragma unroll
        for (int hi = 0; hi < 2; hi++) {
            float l = lsum[mt][hi];
            l += __shfl_xor_sync(0xffffffffu, l, 1);
            l += __shfl_xor_sync(0xffffffffu, l, 2);
            float inv = 1.f / l;
            int qrow = qt*128 + w*32 + mt*16 + g + hi*8;
            float* op = &g_attn[((size_t)(b*SEQ + qrow))*DM + h*HD];
            #pragma unroll
            for (int nt = 0; nt < 4; nt++) {
                float2 o;
                o.x = O[mt][nt][hi*2]   * inv;
                o.y = O[mt][nt][hi*2+1] * inv;
                *(float2*)&op[nt*8 + 2*tg] = o;
            }
        }
}

extern "C" void kernel_launch(void* const* d_in, const int* in_sizes, int n_in,
                              void* d_out, int out_size) {
    const float* x  = (const float*)d_in[0];
    const float* Wq = (const float*)d_in[1];
    const float* bq = (const float*)d_in[2];
    const float* Wk = (const float*)d_in[3];
    const float* bk = (const float*)d_in[4];
    const float* Wv = (const float*)d_in[5];
    const float* bv = (const float*)d_in[6];
    const float* Wo = (const float*)d_in[7];
    const float* bo = (const float*)d_in[8];
    const float* W1 = (const float*)d_in[9];
    const float* b1 = (const float*)d_in[10];
    const float* W2 = (const float*)d_in[11];
    const float* b2 = (const float*)d_in[12];
    float* out = (float*)d_out;

    float *xn1, *q, *k, *v, *attn, *xskip, *xn2, *h1;
    cudaGetSymbolAddress((void**)&xn1,  g_xn1);
    cudaGetSymbolAddress((void**)&q,    g_q);
    cudaGetSymbolAddress((void**)&k,    g_k);
    cudaGetSymbolAddress((void**)&v,    g_v);
    cudaGetSymbolAddress((void**)&attn, g_attn);
    cudaGetSymbolAddress((void**)&xskip,g_xskip);
    cudaGetSymbolAddress((void**)&xn2,  g_xn2);
    cudaGetSymbolAddress((void**)&h1,   g_h1);

    dim3 gD  (DM/128,  MROWS/64);       // (2,128)
    dim3 gQKV(DM/128,  MROWS/64, 3);    // (2,128,3)
    dim3 gF  (DFF/128, MROWS/64);       // (8,128)

    ln_kernel<<<MROWS/8, 256>>>(x, xn1);
    qkv_gemm<<<gQKV, 256>>>(xn1, Wq, bq, q, Wk, bk, k, Wv, bv, v);
    attn_mma<<<dim3(SEQ/128, BB*NH), 128>>>();
    mma_gemm<1><<<gD, 256>>>(attn, Wo, bo, x, xskip, MROWS, DM, DM);
    ln_kernel<<<MROWS/8, 256>>>(xskip, xn2);
    mma_gemm<2><<<gF, 256>>>(xn2, W1, b1, nullptr, h1, MROWS, DFF, DM);
    mma_gemm<3><<<gD, 256>>>(h1, W2, b2, xskip, out, MROWS, DM, DFF);
}

// round 8
// speedup vs baseline: 6.4277x; 1.1608x over previous
#include <cuda_runtime.h>
#include <cuda_fp16.h>
#include <math.h>
#include <stdint.h>
#include <string.h>

#define BB 2
#define SEQ 4096
#define DM 256
#define NH 8
#define HD 32
#define DFF 1024
#define MROWS (BB*SEQ)   // 8192

// ---- scratch (device globals; no allocation allowed) ----
__device__ float g_xn1 [MROWS*DM];
__device__ float g_q   [MROWS*DM];
__device__ float g_k   [MROWS*DM];
__device__ float g_v   [MROWS*DM];
__device__ float g_attn[MROWS*DM];
__device__ float g_xskip[MROWS*DM];
__device__ float g_xn2 [MROWS*DM];
__device__ float g_h1  [MROWS*DFF];

__device__ __forceinline__ void mma16h(float c[4], const uint32_t a[4], const uint32_t b[2]) {
    asm volatile(
        "mma.sync.aligned.m16n8k16.row.col.f32.f16.f16.f32 "
        "{%0,%1,%2,%3}, {%4,%5,%6,%7}, {%8,%9}, {%0,%1,%2,%3};"
        : "+f"(c[0]), "+f"(c[1]), "+f"(c[2]), "+f"(c[3])
        : "r"(a[0]), "r"(a[1]), "r"(a[2]), "r"(a[3]), "r"(b[0]), "r"(b[1]));
}

__device__ __forceinline__ uint32_t pkh2(float lo, float hi){
    __half2 h = __floats2half2_rn(lo, hi);
    uint32_t r; memcpy(&r, &h, 4); return r;
}

__device__ __forceinline__ void ldmx2t(uint32_t &r0, uint32_t &r1, uint32_t saddr){
    asm volatile("ldmatrix.sync.aligned.m8n8.x2.trans.shared.b16 {%0,%1}, [%2];"
                 : "=r"(r0), "=r"(r1) : "r"(saddr));
}

// ---------------- LayerNorm: one warp per row ----------------
__global__ __launch_bounds__(256)
void ln_kernel(const float* __restrict__ x, float* __restrict__ y) {
    int w = threadIdx.x >> 5, lane = threadIdx.x & 31;
    size_t row = (size_t)blockIdx.x*8 + w;
    const float* xr = &x[row*DM];
    float4 v0 = *(const float4*)&xr[lane*4];
    float4 v1 = *(const float4*)&xr[128 + lane*4];
    float s  = v0.x+v0.y+v0.z+v0.w + v1.x+v1.y+v1.z+v1.w;
    float s2 = v0.x*v0.x+v0.y*v0.y+v0.z*v0.z+v0.w*v0.w
             + v1.x*v1.x+v1.y*v1.y+v1.z*v1.z+v1.w*v1.w;
    #pragma unroll
    for (int o = 16; o; o >>= 1) {
        s  += __shfl_xor_sync(0xffffffffu, s,  o);
        s2 += __shfl_xor_sync(0xffffffffu, s2, o);
    }
    float m   = s * (1.0f/DM);
    float var = s2 * (1.0f/DM) - m*m;
    float inv = 1.0f / (sqrtf(fmaxf(var, 0.f)) + 1e-6f);
    float* yr = &y[row*DM];
    float4 o0; o0.x=(v0.x-m)*inv; o0.y=(v0.y-m)*inv; o0.z=(v0.z-m)*inv; o0.w=(v0.w-m)*inv;
    float4 o1; o1.x=(v1.x-m)*inv; o1.y=(v1.y-m)*inv; o1.z=(v1.z-m)*inv; o1.w=(v1.w-m)*inv;
    *(float4*)&yr[lane*4]       = o0;
    *(float4*)&yr[128 + lane*4] = o1;
}

// ---------------- fp16 GEMM: BK=32, double-buffered, 1 sync/iter ----------------
// Block 64x128, 8 warps (2m x 4n), warp tile 32x32.
#define AST 20    // As word stride per row (16 used + pad)
#define BST 136   // Bs word stride per k-pair row
template<int EP>
__device__ __forceinline__
void gemm_body(const float* __restrict__ A, const float* __restrict__ Wm,
               const float* __restrict__ bias, const float* __restrict__ res,
               float* __restrict__ out, int M, int N, int K,
               int bx, int by) {
    __shared__ uint32_t As[2][64*AST];
    __shared__ uint32_t Bs[2][16*BST];
    int tid = threadIdx.x, lane = tid & 31, warp = tid >> 5;
    int wm = warp & 1, wn = warp >> 1;
    int m0 = by * 64, n0 = bx * 128;
    int g = lane >> 2, tg = lane & 3;
    float c[2][4][4];
    #pragma unroll
    for (int i=0;i<2;i++)
        #pragma unroll
        for(int j=0;j<4;j++)
            #pragma unroll
            for(int q=0;q<4;q++) c[i][j][q]=0.f;

    int ar = tid >> 2, aq = tid & 3;        // A: row, 8-float quad
    int bkp = tid >> 4, bq = tid & 15;      // B: k-pair row, 8-col octet
    const int NIT = K >> 5;

    float4 fa0, fa1, fb00, fb01, fb10, fb11;
    const float* Ab0 = &A[(size_t)(m0+ar)*K + aq*8];
    const float* Bb0 = &Wm[(size_t)(2*bkp)*N + n0 + bq*8];

    // prefetch tile 0
    fa0 = *(const float4*)Ab0; fa1 = *(const float4*)(Ab0+4);
    fb00 = *(const float4*)Bb0;     fb01 = *(const float4*)(Bb0+4);
    fb10 = *(const float4*)(Bb0+N); fb11 = *(const float4*)(Bb0+N+4);
    {
        uint4 ua; ua.x=pkh2(fa0.x,fa0.y); ua.y=pkh2(fa0.z,fa0.w);
        ua.z=pkh2(fa1.x,fa1.y); ua.w=pkh2(fa1.z,fa1.w);
        *(uint4*)&As[0][ar*AST + aq*4] = ua;
        uint4 u0; u0.x=pkh2(fb00.x,fb10.x); u0.y=pkh2(fb00.y,fb10.y);
        u0.z=pkh2(fb00.z,fb10.z); u0.w=pkh2(fb00.w,fb10.w);
        uint4 u1; u1.x=pkh2(fb01.x,fb11.x); u1.y=pkh2(fb01.y,fb11.y);
        u1.z=pkh2(fb01.z,fb11.z); u1.w=pkh2(fb01.w,fb11.w);
        *(uint4*)&Bs[0][bkp*BST + bq*8]     = u0;
        *(uint4*)&Bs[0][bkp*BST + bq*8 + 4] = u1;
    }
    __syncthreads();

    for (int it = 0; it < NIT; it++) {
        int cur = it & 1;
        if (it + 1 < NIT) {
            const float* Ab = Ab0 + (it+1)*32;
            const float* Bb = Bb0 + (size_t)(it+1)*32*N;
            fa0 = *(const float4*)Ab; fa1 = *(const float4*)(Ab+4);
            fb00 = *(const float4*)Bb;     fb01 = *(const float4*)(Bb+4);
            fb10 = *(const float4*)(Bb+N); fb11 = *(const float4*)(Bb+N+4);
        }
        #pragma unroll
        for (int kc = 0; kc < 2; kc++) {
            uint32_t a[2][4];
            #pragma unroll
            for (int mt = 0; mt < 2; mt++) {
                int r = wm*32 + mt*16;
                a[mt][0] = As[cur][(r+g  )*AST + kc*8+tg  ];
                a[mt][1] = As[cur][(r+g+8)*AST + kc*8+tg  ];
                a[mt][2] = As[cur][(r+g  )*AST + kc*8+tg+4];
                a[mt][3] = As[cur][(r+g+8)*AST + kc*8+tg+4];
            }
            uint32_t b[4][2];
            #pragma unroll
            for (int nt = 0; nt < 4; nt++) {
                int col = wn*32 + nt*8 + g;
                b[nt][0] = Bs[cur][(kc*8+tg  )*BST + col];
                b[nt][1] = Bs[cur][(kc*8+tg+4)*BST + col];
            }
            #pragma unroll
            for (int mt = 0; mt < 2; mt++)
                #pragma unroll
                for (int nt = 0; nt < 4; nt++)
                    mma16h(c[mt][nt], a[mt], b[nt]);
        }
        if (it + 1 < NIT) {
            int nxt = cur ^ 1;
            uint4 ua; ua.x=pkh2(fa0.x,fa0.y); ua.y=pkh2(fa0.z,fa0.w);
            ua.z=pkh2(fa1.x,fa1.y); ua.w=pkh2(fa1.z,fa1.w);
            *(uint4*)&As[nxt][ar*AST + aq*4] = ua;
            uint4 u0; u0.x=pkh2(fb00.x,fb10.x); u0.y=pkh2(fb00.y,fb10.y);
            u0.z=pkh2(fb00.z,fb10.z); u0.w=pkh2(fb00.w,fb10.w);
            uint4 u1; u1.x=pkh2(fb01.x,fb11.x); u1.y=pkh2(fb01.y,fb11.y);
            u1.z=pkh2(fb01.z,fb11.z); u1.w=pkh2(fb01.w,fb11.w);
            *(uint4*)&Bs[nxt][bkp*BST + bq*8]     = u0;
            *(uint4*)&Bs[nxt][bkp*BST + bq*8 + 4] = u1;
            __syncthreads();
        }
    }

    #pragma unroll
    for (int mt = 0; mt < 2; mt++) {
        #pragma unroll
        for (int nt = 0; nt < 4; nt++) {
            int col = n0 + wn*32 + nt*8 + 2*tg;
            float2 bv = *(const float2*)&bias[col];
            #pragma unroll
            for (int half = 0; half < 2; half++) {
                int row = m0 + wm*32 + mt*16 + g + half*8;
                float v0 = c[mt][nt][half*2+0] + bv.x;
                float v1 = c[mt][nt][half*2+1] + bv.y;
                if (EP == 1 || EP == 3) {
                    float2 rv = *(const float2*)&res[(size_t)row*N + col];
                    v0 += rv.x; v1 += rv.y;
                }
                if (EP == 2) {
                    float i0 = 0.7978845608028654f * (v0 + 0.044715f*v0*v0*v0);
                    float i1 = 0.7978845608028654f * (v1 + 0.044715f*v1*v1*v1);
                    v0 = 0.5f * v0 * (1.0f + tanhf(i0));
                    v1 = 0.5f * v1 * (1.0f + tanhf(i1));
                }
                float2 o; o.x = v0; o.y = v1;
                *(float2*)&out[(size_t)row*N + col] = o;
            }
        }
    }
}

template<int EP>
__global__ __launch_bounds__(256)
void mma_gemm(const float* __restrict__ A, const float* __restrict__ Wm,
              const float* __restrict__ bias, const float* __restrict__ res,
              float* __restrict__ out, int M, int N, int K) {
    gemm_body<EP>(A, Wm, bias, res, out, M, N, K, blockIdx.x, blockIdx.y);
}

__global__ __launch_bounds__(256)
void qkv_gemm(const float* __restrict__ A,
              const float* __restrict__ Wq, const float* __restrict__ bq, float* __restrict__ oq,
              const float* __restrict__ Wk, const float* __restrict__ bk, float* __restrict__ ok,
              const float* __restrict__ Wv, const float* __restrict__ bv, float* __restrict__ ov) {
    const float* W; const float* bi; float* o;
    if (blockIdx.z == 0)      { W = Wq; bi = bq; o = oq; }
    else if (blockIdx.z == 1) { W = Wk; bi = bk; o = ok; }
    else                      { W = Wv; bi = bv; o = ov; }
    gemm_body<0>(A, W, bi, nullptr, o, MROWS, DM, DM, blockIdx.x, blockIdx.y);
}

// ---------------- Flash attention, all-fp16 mma (fp32 accum/softmax) ----------------
#define TSTH 40                         // K/V tile row stride in halves
#define TSTW (TSTH/2)                   // ... in words
#define NT_KEYS (SEQ/64)
#define TILEW (64*TSTW)                 // words per K or V tile

__global__ __launch_bounds__(128)
void attn_mma() {
    __shared__ __align__(16) uint32_t sraw[4*TILEW];   // 2 K bufs + 2 V bufs = 20480 B
    float*  Qs = (float*)sraw;          // [128][33] phase 1 only (16896 B)
    __half* Kb = (__half*)sraw;                         // [2][64][TSTH]
    __half* Vb = (__half*)(sraw + 2*TILEW);             // [2][64][TSTH]

    int qt = blockIdx.x;
    int bh = blockIdx.y;
    int b = bh >> 3, h = bh & 7;
    int tid = threadIdx.x, lane = tid & 31, w = tid >> 5;
    int g = lane >> 2, tg = lane & 3;

    const float scale = 0.17677669529663687f;
    const float* qg = &g_q[((size_t)(b*SEQ + qt*128))*DM + h*HD];
    const float* kg = &g_k[(size_t)b*SEQ*DM + h*HD];
    const float* vg = &g_v[(size_t)b*SEQ*DM + h*HD];

    // ---- Q tile (scaled) -> fp16 A fragments (k16 x 2 chunks) ----
    #pragma unroll
    for (int i = 0; i < 8; i++) {
        int e = tid + i*128;
        int r = e >> 3, c4 = (e & 7)*4;
        float4 v = *(const float4*)&qg[(size_t)r*DM + c4];
        Qs[r*33+c4+0]=v.x*scale; Qs[r*33+c4+1]=v.y*scale;
        Qs[r*33+c4+2]=v.z*scale; Qs[r*33+c4+3]=v.w*scale;
    }
    __syncthreads();
    uint32_t aQ[2][2][4];
    #pragma unroll
    for (int mt = 0; mt < 2; mt++)
        #pragma unroll
        for (int kc = 0; kc < 2; kc++) {
            int r = w*32 + mt*16;
            int k0 = kc*16;
            aQ[mt][kc][0] = pkh2(Qs[(r+g  )*33 + k0+2*tg  ], Qs[(r+g  )*33 + k0+2*tg+1]);
            aQ[mt][kc][1] = pkh2(Qs[(r+g+8)*33 + k0+2*tg  ], Qs[(r+g+8)*33 + k0+2*tg+1]);
            aQ[mt][kc][2] = pkh2(Qs[(r+g  )*33 + k0+2*tg+8], Qs[(r+g  )*33 + k0+2*tg+9]);
            aQ[mt][kc][3] = pkh2(Qs[(r+g+8)*33 + k0+2*tg+8], Qs[(r+g+8)*33 + k0+2*tg+9]);
        }
    __syncthreads();   // Qs region reused as K/V buffers

    float O[2][4][4];
    #pragma unroll
    for (int mt=0;mt<2;mt++)
        #pragma unroll
        for (int nt=0;nt<4;nt++)
            #pragma unroll
            for (int q=0;q<4;q++) O[mt][nt][q]=0.f;
    float m[2][2] = {{-1e30f,-1e30f},{-1e30f,-1e30f}};
    float lsum[2][2] = {{0.f,0.f},{0.f,0.f}};

    // loader: 64x32 tile = 512 float4; 128 thr x 4 float4 each (K and V)
    int pr = tid >> 3, pc = (tid & 7)*4;
    float4 fk[4], fv[4];
    #pragma unroll
    for (int j = 0; j < 4; j++) {
        fk[j] = *(const float4*)&kg[(size_t)(pr + j*16)*DM + pc];
        fv[j] = *(const float4*)&vg[(size_t)(pr + j*16)*DM + pc];
    }
    #pragma unroll
    for (int j = 0; j < 4; j++) {
        int r = pr + j*16;
        uint2 hk; hk.x = pkh2(fk[j].x, fk[j].y); hk.y = pkh2(fk[j].z, fk[j].w);
        uint2 hv; hv.x = pkh2(fv[j].x, fv[j].y); hv.y = pkh2(fv[j].z, fv[j].w);
        *(uint2*)&Kb[r*TSTH + pc] = hk;
        *(uint2*)&Vb[r*TSTH + pc] = hv;
    }
    __syncthreads();

    int ldrow = lane & 15;

    for (int kt = 0; kt < NT_KEYS; kt++) {
        int cur = kt & 1;
        uint32_t* Kc = sraw + cur*TILEW;
        __half*   Vc = Vb + cur*64*TSTH;
        uint32_t vsb = (uint32_t)__cvta_generic_to_shared(Vc) + (uint32_t)(ldrow*TSTH*2);

        if (kt + 1 < NT_KEYS) {
            size_t base = (size_t)(kt+1)*64;
            #pragma unroll
            for (int j = 0; j < 4; j++) {
                fk[j] = *(const float4*)&kg[(base + pr + j*16)*DM + pc];
                fv[j] = *(const float4*)&vg[(base + pr + j*16)*DM + pc];
            }
        }

        // ---- S = Q K^T (fp16 k16) ----
        float c[2][8][4];
        #pragma unroll
        for (int mt=0;mt<2;mt++)
            #pragma unroll
            for (int nt=0;nt<8;nt++)
                #pragma unroll
                for (int q=0;q<4;q++) c[mt][nt][q]=0.f;
        #pragma unroll
        for (int kc = 0; kc < 2; kc++) {
            uint32_t bk[8][2];
            #pragma unroll
            for (int nt = 0; nt < 8; nt++) {
                bk[nt][0] = Kc[(nt*8+g)*TSTW + kc*8+tg  ];
                bk[nt][1] = Kc[(nt*8+g)*TSTW + kc*8+tg+4];
            }
            #pragma unroll
            for (int mt = 0; mt < 2; mt++)
                #pragma unroll
                for (int nt = 0; nt < 8; nt++)
                    mma16h(c[mt][nt], aQ[mt][kc], bk[nt]);
        }

        // ---- online softmax ----
        #pragma unroll
        for (int mt = 0; mt < 2; mt++)
            #pragma unroll
            for (int hi = 0; hi < 2; hi++) {
                float tm = -1e30f;
                #pragma unroll
                for (int nt = 0; nt < 8; nt++) {
                    tm = fmaxf(tm, c[mt][nt][hi*2]);
                    tm = fmaxf(tm, c[mt][nt][hi*2+1]);
                }
                tm = fmaxf(tm, __shfl_xor_sync(0xffffffffu, tm, 1));
                tm = fmaxf(tm, __shfl_xor_sync(0xffffffffu, tm, 2));
                float mn = fmaxf(m[mt][hi], tm);
                float corr = __expf(m[mt][hi] - mn);
                m[mt][hi] = mn;
                lsum[mt][hi] *= corr;
                #pragma unroll
                for (int nt = 0; nt < 4; nt++) {
                    O[mt][nt][hi*2]   *= corr;
                    O[mt][nt][hi*2+1] *= corr;
                }
                float ls = 0.f;
                #pragma unroll
                for (int nt = 0; nt < 8; nt++) {
                    float p0 = __expf(c[mt][nt][hi*2]   - mn);
                    float p1 = __expf(c[mt][nt][hi*2+1] - mn);
                    c[mt][nt][hi*2]   = p0;
                    c[mt][nt][hi*2+1] = p1;
                    ls += p0 + p1;
                }
                lsum[mt][hi] += ls;
            }

        // ---- O += P V (fp16) ----
        #pragma unroll
        for (int kc = 0; kc < 4; kc++) {
            uint32_t aP[2][4];
            #pragma unroll
            for (int mt = 0; mt < 2; mt++) {
                aP[mt][0] = pkh2(c[mt][2*kc  ][0], c[mt][2*kc  ][1]);
                aP[mt][1] = pkh2(c[mt][2*kc  ][2], c[mt][2*kc  ][3]);
                aP[mt][2] = pkh2(c[mt][2*kc+1][0], c[mt][2*kc+1][1]);
                aP[mt][3] = pkh2(c[mt][2*kc+1][2], c[mt][2*kc+1][3]);
            }
            #pragma unroll
            for (int nt = 0; nt < 4; nt++) {
                uint32_t bv[2];
                uint32_t addr = vsb + (uint32_t)(kc*16*TSTH*2 + nt*8*2);
                ldmx2t(bv[0], bv[1], addr);
                mma16h(O[0][nt], aP[0], bv);
                mma16h(O[1][nt], aP[1], bv);
            }
        }

        if (kt + 1 < NT_KEYS) {
            int nxt = (kt+1) & 1;
            __half* Kn = Kb + nxt*64*TSTH;
            __half* Vn = Vb + nxt*64*TSTH;
            #pragma unroll
            for (int j = 0; j < 4; j++) {
                int r = pr + j*16;
                uint2 hk; hk.x = pkh2(fk[j].x, fk[j].y); hk.y = pkh2(fk[j].z, fk[j].w);
                uint2 hv; hv.x = pkh2(fv[j].x, fv[j].y); hv.y = pkh2(fv[j].z, fv[j].w);
                *(uint2*)&Kn[r*TSTH + pc] = hk;
                *(uint2*)&Vn[r*TSTH + pc] = hv;
            }
        }
        __syncthreads();
    }

    #pragma unroll
    for (int mt = 0; mt < 2; mt++)
        #pragma unroll
        for (int hi = 0; hi < 2; hi++) {
            float l = lsum[mt][hi];
            l += __shfl_xor_sync(0xffffffffu, l, 1);
            l += __shfl_xor_sync(0xffffffffu, l, 2);
            float inv = 1.f / l;
            int qrow = qt*128 + w*32 + mt*16 + g + hi*8;
            float* op = &g_attn[((size_t)(b*SEQ + qrow))*DM + h*HD];
            #pragma unroll
            for (int nt = 0; nt < 4; nt++) {
                float2 o;
                o.x = O[mt][nt][hi*2]   * inv;
                o.y = O[mt][nt][hi*2+1] * inv;
                *(float2*)&op[nt*8 + 2*tg] = o;
            }
        }
}

extern "C" void kernel_launch(void* const* d_in, const int* in_sizes, int n_in,
                              void* d_out, int out_size) {
    const float* x  = (const float*)d_in[0];
    const float* Wq = (const float*)d_in[1];
    const float* bq = (const float*)d_in[2];
    const float* Wk = (const float*)d_in[3];
    const float* bk = (const float*)d_in[4];
    const float* Wv = (const float*)d_in[5];
    const float* bv = (const float*)d_in[6];
    const float* Wo = (const float*)d_in[7];
    const float* bo = (const float*)d_in[8];
    const float* W1 = (const float*)d_in[9];
    const float* b1 = (const float*)d_in[10];
    const float* W2 = (const float*)d_in[11];
    const float* b2 = (const float*)d_in[12];
    float* out = (float*)d_out;

    float *xn1, *q, *k, *v, *attn, *xskip, *xn2, *h1;
    cudaGetSymbolAddress((void**)&xn1,  g_xn1);
    cudaGetSymbolAddress((void**)&q,    g_q);
    cudaGetSymbolAddress((void**)&k,    g_k);
    cudaGetSymbolAddress((void**)&v,    g_v);
    cudaGetSymbolAddress((void**)&attn, g_attn);
    cudaGetSymbolAddress((void**)&xskip,g_xskip);
    cudaGetSymbolAddress((void**)&xn2,  g_xn2);
    cudaGetSymbolAddress((void**)&h1,   g_h1);

    dim3 gD  (DM/128,  MROWS/64);       // (2,128)
    dim3 gQKV(DM/128,  MROWS/64, 3);    // (2,128,3)
    dim3 gF  (DFF/128, MROWS/64);       // (8,128)

    ln_kernel<<<MROWS/8, 256>>>(x, xn1);
    qkv_gemm<<<gQKV, 256>>>(xn1, Wq, bq, q, Wk, bk, k, Wv, bv, v);
    attn_mma<<<dim3(SEQ/128, BB*NH), 128>>>();
    mma_gemm<1><<<gD, 256>>>(attn, Wo, bo, x, xskip, MROWS, DM, DM);
    ln_kernel<<<MROWS/8, 256>>>(xskip, xn2);
    mma_gemm<2><<<gF, 256>>>(xn2, W1, b1, nullptr, h1, MROWS, DFF, DM);
    mma_gemm<3><<<gD, 256>>>(h1, W2, b2, xskip, out, MROWS, DM, DFF);
}

// round 10
// speedup vs baseline: 8.6461x; 1.3451x over previous
#include <cuda_runtime.h>
#include <cuda_fp16.h>
#include <math.h>
#include <stdint.h>
#include <string.h>

#define BB 2
#define SEQ 4096
#define DM 256
#define NH 8
#define HD 32
#define DFF 1024
#define MROWS (BB*SEQ)   // 8192

// ---- scratch (device globals; no allocation allowed) ----
__device__ float  g_xskip[MROWS*DM];
__device__ __half g_xn1h [MROWS*DM];
__device__ __half g_qh   [MROWS*DM];
__device__ __half g_kh   [MROWS*DM];
__device__ __half g_vh   [MROWS*DM];
__device__ __half g_attnh[MROWS*DM];
__device__ __half g_xn2h [MROWS*DM];
__device__ __half g_h1h  [MROWS*DFF];
__device__ __half g_hWq[DM*DM], g_hWk[DM*DM], g_hWv[DM*DM], g_hWo[DM*DM];
__device__ __half g_hW1[DM*DFF], g_hW2[DFF*DM];

__device__ __forceinline__ void mma16h(float c[4], const uint32_t a[4], const uint32_t b[2]) {
    asm volatile(
        "mma.sync.aligned.m16n8k16.row.col.f32.f16.f16.f32 "
        "{%0,%1,%2,%3}, {%4,%5,%6,%7}, {%8,%9}, {%0,%1,%2,%3};"
        : "+f"(c[0]), "+f"(c[1]), "+f"(c[2]), "+f"(c[3])
        : "r"(a[0]), "r"(a[1]), "r"(a[2]), "r"(a[3]), "r"(b[0]), "r"(b[1]));
}
__device__ __forceinline__ uint32_t pkh2(float lo, float hi){
    __half2 h = __floats2half2_rn(lo, hi);
    uint32_t r; memcpy(&r, &h, 4); return r;
}
__device__ __forceinline__ void ldmx2t(uint32_t &r0, uint32_t &r1, uint32_t saddr){
    asm volatile("ldmatrix.sync.aligned.m8n8.x2.trans.shared.b16 {%0,%1}, [%2];"
                 : "=r"(r0), "=r"(r1) : "r"(saddr));
}
__device__ __forceinline__ float ex2f(float x){ float r; asm("ex2.approx.f32 %0,%1;":"=f"(r):"f"(x)); return r; }
__device__ __forceinline__ uint32_t ex2h2(uint32_t x){ uint32_t r; asm("ex2.approx.f16x2 %0,%1;":"=r"(r):"r"(x)); return r; }
__device__ __forceinline__ void cpa16(uint32_t dst, const void* src){
    asm volatile("cp.async.cg.shared.global [%0], [%1], 16;" :: "r"(dst), "l"(src));
}
__device__ __forceinline__ void cpcommit(){ asm volatile("cp.async.commit_group;"); }
template<int Ng> __device__ __forceinline__ void cpwait(){ asm volatile("cp.async.wait_group %0;"::"n"(Ng)); }

// ---------------- weight fp32 -> fp16, all six in one launch ----------------
__global__ __launch_bounds__(256)
void w2h_kernel(const float* __restrict__ Wq, const float* __restrict__ Wk,
                const float* __restrict__ Wv, const float* __restrict__ Wo,
                const float* __restrict__ W1, const float* __restrict__ W2) {
    const float* s; __half* d; int n;
    switch (blockIdx.z) {
        case 0: s=Wq; d=g_hWq; n=DM*DM;  break;
        case 1: s=Wk; d=g_hWk; n=DM*DM;  break;
        case 2: s=Wv; d=g_hWv; n=DM*DM;  break;
        case 3: s=Wo; d=g_hWo; n=DM*DM;  break;
        case 4: s=W1; d=g_hW1; n=DM*DFF; break;
        default:s=W2; d=g_hW2; n=DFF*DM; break;
    }
    for (int i = blockIdx.x*blockDim.x + threadIdx.x; i*4 < n; i += gridDim.x*blockDim.x) {
        float4 v = *(const float4*)&s[i*4];
        *(__half2*)&d[i*4]   = __floats2half2_rn(v.x, v.y);
        *(__half2*)&d[i*4+2] = __floats2half2_rn(v.z, v.w);
    }
}

// ---------------- LayerNorm: fp32 in, fp16 out ----------------
__global__ __launch_bounds__(256)
void ln_kernel(const float* __restrict__ x, __half* __restrict__ y) {
    int w = threadIdx.x >> 5, lane = threadIdx.x & 31;
    size_t row = (size_t)blockIdx.x*8 + w;
    const float* xr = &x[row*DM];
    float4 v0 = *(const float4*)&xr[lane*4];
    float4 v1 = *(const float4*)&xr[128 + lane*4];
    float s  = v0.x+v0.y+v0.z+v0.w + v1.x+v1.y+v1.z+v1.w;
    float s2 = v0.x*v0.x+v0.y*v0.y+v0.z*v0.z+v0.w*v0.w
             + v1.x*v1.x+v1.y*v1.y+v1.z*v1.z+v1.w*v1.w;
    #pragma unroll
    for (int o = 16; o; o >>= 1) {
        s  += __shfl_xor_sync(0xffffffffu, s,  o);
        s2 += __shfl_xor_sync(0xffffffffu, s2, o);
    }
    float m   = s * (1.0f/DM);
    float var = s2 * (1.0f/DM) - m*m;
    float inv = 1.0f / (sqrtf(fmaxf(var, 0.f)) + 1e-6f);
    __half* yr = &y[row*DM];
    *(__half2*)&yr[lane*4]       = __floats2half2_rn((v0.x-m)*inv, (v0.y-m)*inv);
    *(__half2*)&yr[lane*4+2]     = __floats2half2_rn((v0.z-m)*inv, (v0.w-m)*inv);
    *(__half2*)&yr[128+lane*4]   = __floats2half2_rn((v1.x-m)*inv, (v1.y-m)*inv);
    *(__half2*)&yr[128+lane*4+2] = __floats2half2_rn((v1.z-m)*inv, (v1.w-m)*inv);
}

// ---------------- fp16 GEMM, cp.async double-buffered ----------------
// Block 64x128, BK=32, 8 warps (2m x 4n). EP0: half out. EP1/3: f32 out+res.
// EP2: gelu half out.
#define ASTH 40     // A smem row stride (halves)
#define BSTH 136    // B smem row stride (halves)
#define ATILEH (64*ASTH)
#define BTILEH (32*BSTH)
template<int EP>
__device__ __forceinline__
void gemm_body(const __half* __restrict__ A, const __half* __restrict__ Wh,
               const float* __restrict__ bias, const float* __restrict__ res,
               void* __restrict__ outv, int M, int N, int K, int bx, int by) {
    __shared__ __align__(16) __half Ah[2*ATILEH];
    __shared__ __align__(16) __half Bh[2*BTILEH];
    int tid = threadIdx.x, lane = tid & 31, warp = tid >> 5;
    int wm = warp & 1, wn = warp >> 1;
    int m0 = by * 64, n0 = bx * 128;
    int g = lane >> 2, tg = lane & 3;
    float c[2][4][4];
    #pragma unroll
    for (int i=0;i<2;i++)
        #pragma unroll
        for(int j=0;j<4;j++)
            #pragma unroll
            for(int q=0;q<4;q++) c[i][j][q]=0.f;

    uint32_t aB = (uint32_t)__cvta_generic_to_shared(Ah);
    uint32_t bB = (uint32_t)__cvta_generic_to_shared(Bh);
    int arow = tid >> 2, aseg = tid & 3;
    int brow = tid >> 4, bseg = tid & 15;
    const __half* Asrc  = &A [(size_t)(m0+arow)*K + aseg*8];
    const __half* Bsrc  = &Wh[(size_t)brow*N + n0 + bseg*8];
    uint32_t adst  = aB + (uint32_t)(arow*ASTH + aseg*8)*2;
    uint32_t bdst  = bB + (uint32_t)(brow*BSTH + bseg*8)*2;
    const int NIT = K >> 5;

    // prologue
    cpa16(adst, Asrc);
    cpa16(bdst, Bsrc);
    cpa16(bdst + 16*BSTH*2, Bsrc + (size_t)16*N);
    cpcommit();

    int ldrow = lane & 15;
    for (int it = 0; it < NIT; it++) {
        int cur = it & 1;
        if (it + 1 < NIT) {
            int nxt = cur ^ 1;
            cpa16(adst + nxt*ATILEH*2, Asrc + (it+1)*32);
            cpa16(bdst + nxt*BTILEH*2, Bsrc + (size_t)(it+1)*32*N);
            cpa16(bdst + (uint32_t)(nxt*BTILEH + 16*BSTH)*2, Bsrc + (size_t)((it+1)*32+16)*N);
            cpcommit();
            cpwait<1>();
        } else {
            cpwait<0>();
        }
        __syncthreads();

        const uint32_t* Aw = (const uint32_t*)&Ah[cur*ATILEH];
        uint32_t bfb = bB + (uint32_t)(cur*BTILEH + ldrow*BSTH)*2;
        #pragma unroll
        for (int kc = 0; kc < 2; kc++) {
            uint32_t a[2][4];
            #pragma unroll
            for (int mt = 0; mt < 2; mt++) {
                int r = wm*32 + mt*16;
                a[mt][0] = Aw[(r+g  )*(ASTH/2) + kc*8 + tg  ];
                a[mt][1] = Aw[(r+g+8)*(ASTH/2) + kc*8 + tg  ];
                a[mt][2] = Aw[(r+g  )*(ASTH/2) + kc*8 + tg+4];
                a[mt][3] = Aw[(r+g+8)*(ASTH/2) + kc*8 + tg+4];
            }
            #pragma unroll
            for (int nt = 0; nt < 4; nt++) {
                uint32_t b[2];
                uint32_t addr = bfb + (uint32_t)(kc*16*BSTH + wn*32 + nt*8)*2;
                ldmx2t(b[0], b[1], addr);
                mma16h(c[0][nt], a[0], b);
                mma16h(c[1][nt], a[1], b);
            }
        }
        if (it + 1 < NIT) __syncthreads();
    }

    #pragma unroll
    for (int mt = 0; mt < 2; mt++) {
        #pragma unroll
        for (int nt = 0; nt < 4; nt++) {
            int col = n0 + wn*32 + nt*8 + 2*tg;
            float2 bv = *(const float2*)&bias[col];
            #pragma unroll
            for (int half = 0; half < 2; half++) {
                int row = m0 + wm*32 + mt*16 + g + half*8;
                float v0 = c[mt][nt][half*2+0] + bv.x;
                float v1 = c[mt][nt][half*2+1] + bv.y;
                if (EP == 1 || EP == 3) {
                    float2 rv = *(const float2*)&res[(size_t)row*N + col];
                    v0 += rv.x; v1 += rv.y;
                    float2 o; o.x = v0; o.y = v1;
                    *(float2*)&((float*)outv)[(size_t)row*N + col] = o;
                } else {
                    if (EP == 2) {
                        float i0 = 0.7978845608028654f * (v0 + 0.044715f*v0*v0*v0);
                        float i1 = 0.7978845608028654f * (v1 + 0.044715f*v1*v1*v1);
                        v0 = 0.5f * v0 * (1.0f + tanhf(i0));
                        v1 = 0.5f * v1 * (1.0f + tanhf(i1));
                    }
                    *(__half2*)&((__half*)outv)[(size_t)row*N + col] = __floats2half2_rn(v0, v1);
                }
            }
        }
    }
}

template<int EP>
__global__ __launch_bounds__(256)
void mma_gemm(const __half* __restrict__ A, const __half* __restrict__ Wh,
              const float* __restrict__ bias, const float* __restrict__ res,
              void* __restrict__ out, int M, int N, int K) {
    gemm_body<EP>(A, Wh, bias, res, out, M, N, K, blockIdx.x, blockIdx.y);
}

__global__ __launch_bounds__(256)
void qkv_gemm(const __half* __restrict__ A,
              const float* __restrict__ bq, const float* __restrict__ bk, const float* __restrict__ bv) {
    const __half* W; const float* bi; __half* o;
    if (blockIdx.z == 0)      { W = g_hWq; bi = bq; o = g_qh; }
    else if (blockIdx.z == 1) { W = g_hWk; bi = bk; o = g_kh; }
    else                      { W = g_hWv; bi = bv; o = g_vh; }
    gemm_body<0>(A, W, bi, nullptr, o, MROWS, DM, DM, blockIdx.x, blockIdx.y);
}

// ---------------- Flash attention, fp16 mma + f16x2 exp2 softmax ----------------
#define TSTH 40
#define TSTW (TSTH/2)
#define NT_KEYS (SEQ/64)
#define TILEW (64*TSTW)

__global__ __launch_bounds__(128)
void attn_mma() {
    __shared__ __align__(16) uint32_t sraw[4*TILEW];   // 20480 B
    float*  Qs = (float*)sraw;                          // phase 1 only (16896 B)
    __half* Kb = (__half*)sraw;
    __half* Vb = (__half*)(sraw + 2*TILEW);

    int qt = blockIdx.x;
    int bh = blockIdx.y;
    int b = bh >> 3, h = bh & 7;
    int tid = threadIdx.x, lane = tid & 31, w = tid >> 5;
    int g = lane >> 2, tg = lane & 3;

    const float scale = 0.2550347251569858f;   // 1/sqrt(32) * log2(e)
    const __half* qg = &g_qh[((size_t)(b*SEQ + qt*128))*DM + h*HD];
    const __half* kg = &g_kh[(size_t)b*SEQ*DM + h*HD];
    const __half* vg = &g_vh[(size_t)b*SEQ*DM + h*HD];

    // ---- Q tile (scaled into log2 domain) -> fp16 A fragments ----
    #pragma unroll
    for (int i = 0; i < 8; i++) {
        int e = tid + i*128;
        int r = e >> 3, c4 = (e & 7)*4;
        uint2 qv = *(const uint2*)&qg[(size_t)r*DM + c4];
        float2 f0 = __half22float2(*(__half2*)&qv.x);
        float2 f1 = __half22float2(*(__half2*)&qv.y);
        Qs[r*33+c4+0]=f0.x*scale; Qs[r*33+c4+1]=f0.y*scale;
        Qs[r*33+c4+2]=f1.x*scale; Qs[r*33+c4+3]=f1.y*scale;
    }
    __syncthreads();
    uint32_t aQ[2][2][4];
    #pragma unroll
    for (int mt = 0; mt < 2; mt++)
        #pragma unroll
        for (int kc = 0; kc < 2; kc++) {
            int r = w*32 + mt*16;
            int k0 = kc*16;
            aQ[mt][kc][0] = pkh2(Qs[(r+g  )*33 + k0+2*tg  ], Qs[(r+g  )*33 + k0+2*tg+1]);
            aQ[mt][kc][1] = pkh2(Qs[(r+g+8)*33 + k0+2*tg  ], Qs[(r+g+8)*33 + k0+2*tg+1]);
            aQ[mt][kc][2] = pkh2(Qs[(r+g  )*33 + k0+2*tg+8], Qs[(r+g  )*33 + k0+2*tg+9]);
            aQ[mt][kc][3] = pkh2(Qs[(r+g+8)*33 + k0+2*tg+8], Qs[(r+g+8)*33 + k0+2*tg+9]);
        }
    __syncthreads();   // Qs region reused as K/V buffers

    float O[2][4][4];
    #pragma unroll
    for (int mt=0;mt<2;mt++)
        #pragma unroll
        for (int nt=0;nt<4;nt++)
            #pragma unroll
            for (int q=0;q<4;q++) O[mt][nt][q]=0.f;
    float m[2][2] = {{-1e30f,-1e30f},{-1e30f,-1e30f}};
    float lsum[2][2] = {{0.f,0.f},{0.f,0.f}};

    // loader: 64x32 halves per tile; 128 thr x 4 x uint2 each (K and V)
    int pr = tid >> 3, pc = (tid & 7)*4;
    uint2 fk[4], fv[4];
    #pragma unroll
    for (int j = 0; j < 4; j++) {
        fk[j] = *(const uint2*)&kg[(size_t)(pr + j*16)*DM + pc];
        fv[j] = *(const uint2*)&vg[(size_t)(pr + j*16)*DM + pc];
    }
    #pragma unroll
    for (int j = 0; j < 4; j++) {
        int r = pr + j*16;
        *(uint2*)&Kb[r*TSTH + pc] = fk[j];
        *(uint2*)&Vb[r*TSTH + pc] = fv[j];
    }
    __syncthreads();

    int ldrow = lane & 15;

    for (int kt = 0; kt < NT_KEYS; kt++) {
        int cur = kt & 1;
        uint32_t* Kc = sraw + cur*TILEW;
        __half*   Vc = Vb + cur*64*TSTH;
        uint32_t vsb = (uint32_t)__cvta_generic_to_shared(Vc) + (uint32_t)(ldrow*TSTH*2);

        if (kt + 1 < NT_KEYS) {
            size_t base = (size_t)(kt+1)*64;
            #pragma unroll
            for (int j = 0; j < 4; j++) {
                fk[j] = *(const uint2*)&kg[(base + pr + j*16)*DM + pc];
                fv[j] = *(const uint2*)&vg[(base + pr + j*16)*DM + pc];
            }
        }

        // ---- S = Q K^T (fp16, log2-domain scores) ----
        float c[2][8][4];
        #pragma unroll
        for (int mt=0;mt<2;mt++)
            #pragma unroll
            for (int nt=0;nt<8;nt++)
                #pragma unroll
                for (int q=0;q<4;q++) c[mt][nt][q]=0.f;
        #pragma unroll
        for (int kc = 0; kc < 2; kc++) {
            uint32_t bk[8][2];
            #pragma unroll
            for (int nt = 0; nt < 8; nt++) {
                bk[nt][0] = Kc[(nt*8+g)*TSTW + kc*8+tg  ];
                bk[nt][1] = Kc[(nt*8+g)*TSTW + kc*8+tg+4];
            }
            #pragma unroll
            for (int mt = 0; mt < 2; mt++)
                #pragma unroll
                for (int nt = 0; nt < 8; nt++)
                    mma16h(c[mt][nt], aQ[mt][kc], bk[nt]);
        }

        // ---- online softmax (base-2) ----
        #pragma unroll
        for (int mt = 0; mt < 2; mt++)
            #pragma unroll
            for (int hi = 0; hi < 2; hi++) {
                float tm = -1e30f;
                #pragma unroll
                for (int nt = 0; nt < 8; nt++) {
                    tm = fmaxf(tm, c[mt][nt][hi*2]);
                    tm = fmaxf(tm, c[mt][nt][hi*2+1]);
                }
                tm = fmaxf(tm, __shfl_xor_sync(0xffffffffu, tm, 1));
                tm = fmaxf(tm, __shfl_xor_sync(0xffffffffu, tm, 2));
                float mn = fmaxf(m[mt][hi], tm);
                float corr = ex2f(m[mt][hi] - mn);
                m[mt][hi] = mn;
                lsum[mt][hi] *= corr;
                #pragma unroll
                for (int nt = 0; nt < 4; nt++) {
                    O[mt][nt][hi*2]   *= corr;
                    O[mt][nt][hi*2+1] *= corr;
                }
            }
        // exp2 in f16x2; result doubles as the packed PV A-fragment
        #pragma unroll
        for (int mt = 0; mt < 2; mt++) {
            float ls0 = 0.f, ls1 = 0.f;
            #pragma unroll
            for (int nt = 0; nt < 8; nt++) {
                uint32_t p0 = ex2h2(pkh2(c[mt][nt][0]-m[mt][0], c[mt][nt][1]-m[mt][0]));
                uint32_t p1 = ex2h2(pkh2(c[mt][nt][2]-m[mt][1], c[mt][nt][3]-m[mt][1]));
                __half2 h0, h1; memcpy(&h0, &p0, 4); memcpy(&h1, &p1, 4);
                float2 f0 = __half22float2(h0), f1 = __half22float2(h1);
                ls0 += f0.x + f0.y;  ls1 += f1.x + f1.y;
                c[mt][nt][0] = __uint_as_float(p0);
                c[mt][nt][1] = __uint_as_float(p1);
            }
            lsum[mt][0] += ls0; lsum[mt][1] += ls1;
        }

        // ---- O += P V (fp16) ----
        #pragma unroll
        for (int kc = 0; kc < 4; kc++) {
            uint32_t aP[2][4];
            #pragma unroll
            for (int mt = 0; mt < 2; mt++) {
                aP[mt][0] = __float_as_uint(c[mt][2*kc  ][0]);
                aP[mt][1] = __float_as_uint(c[mt][2*kc  ][1]);
                aP[mt][2] = __float_as_uint(c[mt][2*kc+1][0]);
                aP[mt][3] = __float_as_uint(c[mt][2*kc+1][1]);
            }
            #pragma unroll
            for (int nt = 0; nt < 4; nt++) {
                uint32_t bv[2];
                uint32_t addr = vsb + (uint32_t)(kc*16*TSTH*2 + nt*8*2);
                ldmx2t(bv[0], bv[1], addr);
                mma16h(O[0][nt], aP[0], bv);
                mma16h(O[1][nt], aP[1], bv);
            }
        }

        if (kt + 1 < NT_KEYS) {
            int nxt = (kt+1) & 1;
            __half* Kn = (__half*)(sraw + nxt*TILEW);
            __half* Vn = Vb + nxt*64*TSTH;
            #pragma unroll
            for (int j = 0; j < 4; j++) {
                int r = pr + j*16;
                *(uint2*)&Kn[r*TSTH + pc] = fk[j];
                *(uint2*)&Vn[r*TSTH + pc] = fv[j];
            }
        }
        __syncthreads();
    }

    #pragma unroll
    for (int mt = 0; mt < 2; mt++)
        #pragma unroll
        for (int hi = 0; hi < 2; hi++) {
            float l = lsum[mt][hi];
            l += __shfl_xor_sync(0xffffffffu, l, 1);
            l += __shfl_xor_sync(0xffffffffu, l, 2);
            float inv = 1.f / l;
            int qrow = qt*128 + w*32 + mt*16 + g + hi*8;
            __half* op = &g_attnh[((size_t)(b*SEQ + qrow))*DM + h*HD];
            #pragma unroll
            for (int nt = 0; nt < 4; nt++)
                *(__half2*)&op[nt*8 + 2*tg] =
                    __floats2half2_rn(O[mt][nt][hi*2]*inv, O[mt][nt][hi*2+1]*inv);
        }
}

extern "C" void kernel_launch(void* const* d_in, const int* in_sizes, int n_in,
                              void* d_out, int out_size) {
    const float* x  = (const float*)d_in[0];
    const float* Wq = (const float*)d_in[1];
    const float* bq = (const float*)d_in[2];
    const float* Wk = (const float*)d_in[3];
    const float* bk = (const float*)d_in[4];
    const float* Wv = (const float*)d_in[5];
    const float* bv = (const float*)d_in[6];
    const float* Wo = (const float*)d_in[7];
    const float* bo = (const float*)d_in[8];
    const float* W1 = (const float*)d_in[9];
    const float* b1 = (const float*)d_in[10];
    const float* W2 = (const float*)d_in[11];
    const float* b2 = (const float*)d_in[12];
    float* out = (float*)d_out;

    float *xskip; __half *xn1h, *attnh, *xn2h, *h1h, *hWo, *hW1, *hW2;
    cudaGetSymbolAddress((void**)&xskip, g_xskip);
    cudaGetSymbolAddress((void**)&xn1h,  g_xn1h);
    cudaGetSymbolAddress((void**)&attnh, g_attnh);
    cudaGetSymbolAddress((void**)&xn2h,  g_xn2h);
    cudaGetSymbolAddress((void**)&h1h,   g_h1h);
    cudaGetSymbolAddress((void**)&hWo,   g_hWo);
    cudaGetSymbolAddress((void**)&hW1,   g_hW1);
    cudaGetSymbolAddress((void**)&hW2,   g_hW2);

    dim3 gD  (DM/128,  MROWS/64);       // (2,128)
    dim3 gQKV(DM/128,  MROWS/64, 3);    // (2,128,3)
    dim3 gF  (DFF/128, MROWS/64);       // (8,128)

    w2h_kernel<<<dim3(64,1,6), 256>>>(Wq, Wk, Wv, Wo, W1, W2);
    ln_kernel<<<MROWS/8, 256>>>(x, xn1h);
    qkv_gemm<<<gQKV, 256>>>(xn1h, bq, bk, bv);
    attn_mma<<<dim3(SEQ/128, BB*NH), 128>>>();
    mma_gemm<1><<<gD, 256>>>(attnh, hWo, bo, x, xskip, MROWS, DM, DM);
    ln_kernel<<<MROWS/8, 256>>>(xskip, xn2h);
    mma_gemm<2><<<gF, 256>>>(xn2h, hW1, b1, nullptr, h1h, MROWS, DFF, DM);
    mma_gemm<3><<<gD, 256>>>(h1h, hW2, b2, xskip, out, MROWS, DM, DFF);
}